// round 1
// baseline (speedup 1.0000x reference)
#include <cuda_runtime.h>
#include <cuda_bf16.h>
#include <math.h>

// Problem dims
#define BB   4
#define SS   2048
#define DD   1024
#define HH   16
#define DKK  64
#define DOUTT 1024
#define MM   (BB*SS)          // 8192
#define N3   (3*HH*DKK)       // 3072 packed QKV width

// -------- scratch (no cudaMalloc allowed) --------
__device__ float g_Wqkv[DD * N3];          // packed weights [D][3072]  (12 MB)
__device__ float g_bqkv[N3];               // packed bias
__device__ float g_QKV[(size_t)MM * N3];   // [8192][3072]  Q|K|V      (96 MB)
__device__ float g_cat[(size_t)MM * DOUTT];// [8192][1024] concat heads (32 MB)

// ============================================================
// Kernel 1: repack Wq/Wk/Wv [H,D,DK] -> [D, 3*1024], pack biases
// ============================================================
__global__ void pack_weights_kernel(const float* __restrict__ Wq,
                                    const float* __restrict__ bq,
                                    const float* __restrict__ Wk,
                                    const float* __restrict__ bk,
                                    const float* __restrict__ Wv,
                                    const float* __restrict__ bv) {
    int idx = blockIdx.x * blockDim.x + threadIdx.x;
    const int per = DD * HH * DKK;   // 1048576
    if (idx < 3 * per) {
        int which = idx / per;
        int rem   = idx % per;
        int d = rem >> 10;           // /1024
        int c = rem & 1023;
        int h = c >> 6;
        int k = c & 63;
        const float* W = (which == 0) ? Wq : (which == 1) ? Wk : Wv;
        g_Wqkv[(size_t)d * N3 + which * 1024 + c] = W[h * (DD * DKK) + d * DKK + k];
    }
    if (idx < N3) {
        int which = idx >> 10;
        int c = idx & 1023;
        const float* bsrc = (which == 0) ? bq : (which == 1) ? bk : bv;
        g_bqkv[idx] = bsrc[c];
    }
}

// ============================================================
// Kernel 2: SGEMM  C[M][N] = A[M][K] * Bw[K][N] + bias[N]
// row-major everything, M%128==0, N%128==0, K%16==0
// block 256 threads, 128x128 tile, 8x8 per thread, BK=16
// ============================================================
__global__ __launch_bounds__(256) void sgemm_bias_kernel(
    const float* __restrict__ A, const float* __restrict__ Bw,
    const float* __restrict__ bias, float* __restrict__ C,
    int M, int N, int K)
{
    const int BM = 128, BN = 128, BK = 16;
    __shared__ float As[BK][BM];   // transposed A tile
    __shared__ float Bs[BK][BN];

    int tid = threadIdx.x;
    int tx = tid & 15;
    int ty = tid >> 4;
    int row0 = blockIdx.y * BM + ty * 8;
    int col0 = blockIdx.x * BN + tx * 8;

    const float* Aptr = A + (size_t)(blockIdx.y * BM) * K;
    const float* Bptr = Bw + blockIdx.x * BN;

    float acc[8][8];
    #pragma unroll
    for (int i = 0; i < 8; i++)
        #pragma unroll
        for (int j = 0; j < 8; j++) acc[i][j] = 0.0f;

    for (int kt = 0; kt < K; kt += BK) {
        // load A tile (128 rows x 16 k) as float4, store transposed
        #pragma unroll
        for (int L = 0; L < 2; L++) {
            int idx = tid + L * 256;
            int r  = idx >> 2;          // 0..127
            int kk = (idx & 3) << 2;    // 0,4,8,12
            float4 v = *(const float4*)(Aptr + (size_t)r * K + kt + kk);
            As[kk + 0][r] = v.x;
            As[kk + 1][r] = v.y;
            As[kk + 2][r] = v.z;
            As[kk + 3][r] = v.w;
        }
        // load B tile (16 k x 128 n)
        #pragma unroll
        for (int L = 0; L < 2; L++) {
            int idx = tid + L * 256;
            int kk = idx >> 5;          // 0..15
            int n4 = (idx & 31) << 2;   // 0..124
            *(float4*)&Bs[kk][n4] = *(const float4*)(Bptr + (size_t)(kt + kk) * N + n4);
        }
        __syncthreads();

        #pragma unroll
        for (int k = 0; k < BK; k++) {
            float a[8], b[8];
            *(float4*)&a[0] = *(const float4*)&As[k][ty * 8];
            *(float4*)&a[4] = *(const float4*)&As[k][ty * 8 + 4];
            *(float4*)&b[0] = *(const float4*)&Bs[k][tx * 8];
            *(float4*)&b[4] = *(const float4*)&Bs[k][tx * 8 + 4];
            #pragma unroll
            for (int i = 0; i < 8; i++)
                #pragma unroll
                for (int j = 0; j < 8; j++)
                    acc[i][j] = fmaf(a[i], b[j], acc[i][j]);
        }
        __syncthreads();
    }

    float br[8];
    #pragma unroll
    for (int j = 0; j < 8; j++) br[j] = bias[col0 + j];

    #pragma unroll
    for (int i = 0; i < 8; i++) {
        float4 v0, v1;
        v0.x = acc[i][0] + br[0]; v0.y = acc[i][1] + br[1];
        v0.z = acc[i][2] + br[2]; v0.w = acc[i][3] + br[3];
        v1.x = acc[i][4] + br[4]; v1.y = acc[i][5] + br[5];
        v1.z = acc[i][6] + br[6]; v1.w = acc[i][7] + br[7];
        float* Cp = C + (size_t)(row0 + i) * N + col0;
        *(float4*)(Cp)     = v0;
        *(float4*)(Cp + 4) = v1;
    }
}

// ============================================================
// Kernel 3: flash attention, fp32.
// grid = (S/64, B*H), block = 256.
// Q tile 64x64 (pre-scaled), stream K/V tiles of 64.
// smem: Qs[64][64] | KVs[64][65] (K^T then V) | Ps[64][64]
// thread (ty,tx): 4 q-rows (ty*4..) x 4 cols (tx*4..)
// ============================================================
#define ATT_SMEM_FLOATS (64*64 + 64*65 + 64*64)   // 12352 floats = 49408 B

__global__ __launch_bounds__(256) void attn_kernel(const float* __restrict__ QKV,
                                                   float* __restrict__ cat)
{
    extern __shared__ float sm[];
    float* Qs  = sm;                 // [64][64]
    float* KVs = sm + 64 * 64;       // [64][65]
    float* Ps  = sm + 64 * 64 + 64 * 65; // [64][64]

    int tid = threadIdx.x;
    int tx = tid & 15;
    int ty = tid >> 4;
    int bh = blockIdx.y;
    int b = bh >> 4;
    int h = bh & 15;
    int s0 = blockIdx.x * 64;

    const float* Qbase = QKV + (size_t)(b * SS) * N3 + h * DKK;
    const float* Kbase = Qbase + 1024;
    const float* Vbase = Qbase + 2048;

    // load Q tile, pre-scale by 1/sqrt(DK)
    #pragma unroll
    for (int L = 0; L < 4; L++) {
        int idx = tid + L * 256;
        int r  = idx >> 4;
        int q4 = (idx & 15) << 2;
        float4 v = *(const float4*)(Qbase + (size_t)(s0 + r) * N3 + q4);
        v.x *= 0.125f; v.y *= 0.125f; v.z *= 0.125f; v.w *= 0.125f;
        *(float4*)&Qs[r * 64 + q4] = v;
    }

    float o[4][4];
    float m_run[4], l_run[4];
    #pragma unroll
    for (int i = 0; i < 4; i++) {
        m_run[i] = -1e30f; l_run[i] = 0.0f;
        #pragma unroll
        for (int j = 0; j < 4; j++) o[i][j] = 0.0f;
    }
    int r0 = ty * 4, c0 = tx * 4;

    for (int kt = 0; kt < SS; kt += 64) {
        // load K tile transposed: KVs[k][c] = K[kt+c][k]
        #pragma unroll
        for (int L = 0; L < 4; L++) {
            int idx = tid + L * 256;
            int r  = idx >> 4;
            int k4 = (idx & 15) << 2;
            float4 v = *(const float4*)(Kbase + (size_t)(kt + r) * N3 + k4);
            KVs[(k4 + 0) * 65 + r] = v.x;
            KVs[(k4 + 1) * 65 + r] = v.y;
            KVs[(k4 + 2) * 65 + r] = v.z;
            KVs[(k4 + 3) * 65 + r] = v.w;
        }
        __syncthreads();

        // S = Q * K^T (scaled already)
        float p[4][4];
        #pragma unroll
        for (int i = 0; i < 4; i++)
            #pragma unroll
            for (int j = 0; j < 4; j++) p[i][j] = 0.0f;

        #pragma unroll 8
        for (int k = 0; k < 64; k++) {
            float q[4], kk[4];
            #pragma unroll
            for (int i = 0; i < 4; i++) q[i] = Qs[(r0 + i) * 64 + k];
            #pragma unroll
            for (int j = 0; j < 4; j++) kk[j] = KVs[k * 65 + c0 + j];
            #pragma unroll
            for (int i = 0; i < 4; i++)
                #pragma unroll
                for (int j = 0; j < 4; j++)
                    p[i][j] = fmaf(q[i], kk[j], p[i][j]);
        }

        // online softmax update (reduce over 16 tx-lanes within half-warp)
        float alpha[4];
        #pragma unroll
        for (int i = 0; i < 4; i++) {
            float mloc = fmaxf(fmaxf(p[i][0], p[i][1]), fmaxf(p[i][2], p[i][3]));
            #pragma unroll
            for (int off = 8; off >= 1; off >>= 1)
                mloc = fmaxf(mloc, __shfl_xor_sync(0xffffffffu, mloc, off));
            float mnew = fmaxf(m_run[i], mloc);
            alpha[i] = __expf(m_run[i] - mnew);
            float rs = 0.0f;
            #pragma unroll
            for (int j = 0; j < 4; j++) {
                p[i][j] = __expf(p[i][j] - mnew);
                rs += p[i][j];
            }
            #pragma unroll
            for (int off = 8; off >= 1; off >>= 1)
                rs += __shfl_xor_sync(0xffffffffu, rs, off);
            l_run[i] = l_run[i] * alpha[i] + rs;
            m_run[i] = mnew;
            #pragma unroll
            for (int j = 0; j < 4; j++) o[i][j] *= alpha[i];
        }
        __syncthreads();   // done reading K from KVs

        // stage P, load V into KVs (natural layout [t][dk], stride 65)
        #pragma unroll
        for (int i = 0; i < 4; i++) {
            float4 v; v.x = p[i][0]; v.y = p[i][1]; v.z = p[i][2]; v.w = p[i][3];
            *(float4*)&Ps[(r0 + i) * 64 + c0] = v;
        }
        #pragma unroll
        for (int L = 0; L < 4; L++) {
            int idx = tid + L * 256;
            int r  = idx >> 4;
            int v4 = (idx & 15) << 2;
            float4 v = *(const float4*)(Vbase + (size_t)(kt + r) * N3 + v4);
            KVs[r * 65 + v4 + 0] = v.x;
            KVs[r * 65 + v4 + 1] = v.y;
            KVs[r * 65 + v4 + 2] = v.z;
            KVs[r * 65 + v4 + 3] = v.w;
        }
        __syncthreads();

        // O += P * V
        #pragma unroll 8
        for (int t = 0; t < 64; t++) {
            float pr[4], vv[4];
            #pragma unroll
            for (int i = 0; i < 4; i++) pr[i] = Ps[(r0 + i) * 64 + t];
            #pragma unroll
            for (int j = 0; j < 4; j++) vv[j] = KVs[t * 65 + c0 + j];
            #pragma unroll
            for (int i = 0; i < 4; i++)
                #pragma unroll
                for (int j = 0; j < 4; j++)
                    o[i][j] = fmaf(pr[i], vv[j], o[i][j]);
        }
        __syncthreads();   // protect KVs/Ps before next iteration
    }

    // normalize + write to concat layout [B,S,H*DK]
    #pragma unroll
    for (int i = 0; i < 4; i++) {
        float inv = 1.0f / l_run[i];
        float4 v;
        v.x = o[i][0] * inv; v.y = o[i][1] * inv;
        v.z = o[i][2] * inv; v.w = o[i][3] * inv;
        *(float4*)(cat + (size_t)(b * SS + s0 + r0 + i) * DOUTT + h * DKK + c0) = v;
    }
}

// ============================================================
// launch
// ============================================================
extern "C" void kernel_launch(void* const* d_in, const int* in_sizes, int n_in,
                              void* d_out, int out_size) {
    const float* x  = (const float*)d_in[0];
    const float* Wq = (const float*)d_in[1];
    const float* bq = (const float*)d_in[2];
    const float* Wk = (const float*)d_in[3];
    const float* bk = (const float*)d_in[4];
    const float* Wv = (const float*)d_in[5];
    const float* bv = (const float*)d_in[6];
    const float* Wo = (const float*)d_in[7];
    const float* bo = (const float*)d_in[8];
    float* out = (float*)d_out;

    float *pWqkv, *pbqkv, *pQKV, *pcat;
    cudaGetSymbolAddress((void**)&pWqkv, g_Wqkv);
    cudaGetSymbolAddress((void**)&pbqkv, g_bqkv);
    cudaGetSymbolAddress((void**)&pQKV,  g_QKV);
    cudaGetSymbolAddress((void**)&pcat,  g_cat);

    // 1) pack weights
    {
        int total = 3 * DD * HH * DKK;
        pack_weights_kernel<<<(total + 255) / 256, 256>>>(Wq, bq, Wk, bk, Wv, bv);
    }
    // 2) QKV projection: [8192,1024] x [1024,3072] + b
    {
        dim3 grid(N3 / 128, MM / 128);
        sgemm_bias_kernel<<<grid, 256>>>(x, pWqkv, pbqkv, pQKV, MM, N3, DD);
    }
    // 3) attention
    {
        cudaFuncSetAttribute(attn_kernel, cudaFuncAttributeMaxDynamicSharedMemorySize,
                             ATT_SMEM_FLOATS * (int)sizeof(float));
        dim3 grid(SS / 64, BB * HH);
        attn_kernel<<<grid, 256, ATT_SMEM_FLOATS * sizeof(float)>>>(pQKV, pcat);
    }
    // 4) output projection: [8192,1024] x [1024,1024] + bo
    {
        dim3 grid(DOUTT / 128, MM / 128);
        sgemm_bias_kernel<<<grid, 256>>>(pcat, Wo, bo, out, MM, DOUTT, DD);
    }
}

// round 2
// speedup vs baseline: 2.5187x; 2.5187x over previous
#include <cuda_runtime.h>
#include <cuda_bf16.h>
#include <math.h>

// Problem dims
#define BB   4
#define SS   2048
#define DD   1024
#define HH   16
#define DKK  64
#define DOUTT 1024
#define MM   (BB*SS)          // 8192
#define N3   (3*HH*DKK)       // 3072

// -------- scratch --------
__device__ float g_Wqkv[DD * N3];
__device__ float g_bqkv[N3];
__device__ float g_QKV[(size_t)MM * N3];
__device__ float g_cat[(size_t)MM * DOUTT];

__device__ __forceinline__ unsigned f2tf32(float x) {
    unsigned r;
    asm("cvt.rna.tf32.f32 %0, %1;" : "=r"(r) : "f"(x));
    return r;
}

__device__ __forceinline__ void mma_tf32(float& c0, float& c1, float& c2, float& c3,
                                         unsigned a0, unsigned a1, unsigned a2, unsigned a3,
                                         unsigned b0, unsigned b1) {
    asm volatile(
        "mma.sync.aligned.m16n8k8.row.col.f32.tf32.tf32.f32 "
        "{%0,%1,%2,%3}, {%4,%5,%6,%7}, {%8,%9}, {%0,%1,%2,%3};\n"
        : "+f"(c0), "+f"(c1), "+f"(c2), "+f"(c3)
        : "r"(a0), "r"(a1), "r"(a2), "r"(a3), "r"(b0), "r"(b1));
}

// ============================================================
// Kernel 1: pack weights
// ============================================================
__global__ void pack_weights_kernel(const float* __restrict__ Wq,
                                    const float* __restrict__ bq,
                                    const float* __restrict__ Wk,
                                    const float* __restrict__ bk,
                                    const float* __restrict__ Wv,
                                    const float* __restrict__ bv) {
    int idx = blockIdx.x * blockDim.x + threadIdx.x;
    const int per = DD * HH * DKK;
    if (idx < 3 * per) {
        int which = idx / per;
        int rem   = idx % per;
        int d = rem >> 10;
        int c = rem & 1023;
        int h = c >> 6;
        int k = c & 63;
        const float* W = (which == 0) ? Wq : (which == 1) ? Wk : Wv;
        g_Wqkv[(size_t)d * N3 + which * 1024 + c] = W[h * (DD * DKK) + d * DKK + k];
    }
    if (idx < N3) {
        int which = idx >> 10;
        int c = idx & 1023;
        const float* bsrc = (which == 0) ? bq : (which == 1) ? bk : bv;
        g_bqkv[idx] = bsrc[c];
    }
}

// ============================================================
// Kernel 2: TF32 tensor-core GEMM  C = A[M,K] * B[K,N] + bias
// block 256 (8 warps), tile 128x128, BK=16
// warp grid 4(m) x 2(n): warp tile 32x64
// ============================================================
#define AS_STRIDE 20
#define BS_STRIDE 132

__global__ __launch_bounds__(256) void gemm_tf32_kernel(
    const float* __restrict__ A, const float* __restrict__ Bw,
    const float* __restrict__ bias, float* __restrict__ C,
    int M, int N, int K)
{
    __shared__ unsigned As[128 * AS_STRIDE];   // [m][k] stride 20
    __shared__ unsigned Bs[16 * BS_STRIDE];    // [k][n] stride 132

    int tid  = threadIdx.x;
    int lane = tid & 31;
    int w    = tid >> 5;
    int warp_m = w >> 1;          // 0..3 -> m offset *32
    int warp_n = w & 1;           // 0..1 -> n offset *64
    int lg = lane >> 2;           // 0..7
    int lq = lane & 3;            // 0..3

    const float* Aptr = A + (size_t)(blockIdx.y * 128) * K;
    const float* Bptr = Bw + blockIdx.x * 128;

    float acc[2][8][4];
    #pragma unroll
    for (int mt = 0; mt < 2; mt++)
        #pragma unroll
        for (int nt = 0; nt < 8; nt++)
            #pragma unroll
            for (int r = 0; r < 4; r++) acc[mt][nt][r] = 0.0f;

    for (int kt = 0; kt < K; kt += 16) {
        // A tile: 128x16
        #pragma unroll
        for (int L = 0; L < 2; L++) {
            int idx = tid + L * 256;
            int r  = idx >> 2;
            int kk = (idx & 3) << 2;
            float4 v = *(const float4*)(Aptr + (size_t)r * K + kt + kk);
            As[r * AS_STRIDE + kk + 0] = f2tf32(v.x);
            As[r * AS_STRIDE + kk + 1] = f2tf32(v.y);
            As[r * AS_STRIDE + kk + 2] = f2tf32(v.z);
            As[r * AS_STRIDE + kk + 3] = f2tf32(v.w);
        }
        // B tile: 16x128
        #pragma unroll
        for (int L = 0; L < 2; L++) {
            int idx = tid + L * 256;
            int kk = idx >> 5;
            int n4 = (idx & 31) << 2;
            float4 v = *(const float4*)(Bptr + (size_t)(kt + kk) * N + n4);
            Bs[kk * BS_STRIDE + n4 + 0] = f2tf32(v.x);
            Bs[kk * BS_STRIDE + n4 + 1] = f2tf32(v.y);
            Bs[kk * BS_STRIDE + n4 + 2] = f2tf32(v.z);
            Bs[kk * BS_STRIDE + n4 + 3] = f2tf32(v.w);
        }
        __syncthreads();

        #pragma unroll
        for (int ks = 0; ks < 2; ks++) {
            int k0 = ks * 8;
            unsigned af[2][4];
            #pragma unroll
            for (int mt = 0; mt < 2; mt++) {
                int mb = warp_m * 32 + mt * 16;
                af[mt][0] = As[(mb + lg) * AS_STRIDE + k0 + lq];
                af[mt][1] = As[(mb + 8 + lg) * AS_STRIDE + k0 + lq];
                af[mt][2] = As[(mb + lg) * AS_STRIDE + k0 + 4 + lq];
                af[mt][3] = As[(mb + 8 + lg) * AS_STRIDE + k0 + 4 + lq];
            }
            #pragma unroll
            for (int nt = 0; nt < 8; nt++) {
                int nb = warp_n * 64 + nt * 8;
                unsigned b0 = Bs[(k0 + lq) * BS_STRIDE + nb + lg];
                unsigned b1 = Bs[(k0 + 4 + lq) * BS_STRIDE + nb + lg];
                #pragma unroll
                for (int mt = 0; mt < 2; mt++)
                    mma_tf32(acc[mt][nt][0], acc[mt][nt][1], acc[mt][nt][2], acc[mt][nt][3],
                             af[mt][0], af[mt][1], af[mt][2], af[mt][3], b0, b1);
            }
        }
        __syncthreads();
    }

    // epilogue
    #pragma unroll
    for (int mt = 0; mt < 2; mt++) {
        int row0 = blockIdx.y * 128 + warp_m * 32 + mt * 16 + lg;
        #pragma unroll
        for (int nt = 0; nt < 8; nt++) {
            int col = blockIdx.x * 128 + warp_n * 64 + nt * 8 + 2 * lq;
            float b0 = bias[col], b1 = bias[col + 1];
            float2 v0 = make_float2(acc[mt][nt][0] + b0, acc[mt][nt][1] + b1);
            float2 v1 = make_float2(acc[mt][nt][2] + b0, acc[mt][nt][3] + b1);
            *(float2*)(C + (size_t)row0 * N + col) = v0;
            *(float2*)(C + (size_t)(row0 + 8) * N + col) = v1;
        }
    }
}

// ============================================================
// Kernel 3: tensor-core flash attention (tf32)
// block 128 (4 warps), Q tile 64 rows; warp w owns rows [w*16, w*16+16)
// ============================================================
#define QS_STR 68
#define ATT_SMEM_BYTES (4 * 64 * QS_STR * 4)   // Qs,Ks,Vs,Ps

__global__ __launch_bounds__(128) void attn_tc_kernel(const float* __restrict__ QKV,
                                                      float* __restrict__ cat)
{
    extern __shared__ unsigned smu[];
    unsigned* Qs = smu;
    unsigned* Ks = smu + 64 * QS_STR;
    unsigned* Vs = smu + 2 * 64 * QS_STR;
    unsigned* Ps = smu + 3 * 64 * QS_STR;

    int tid  = threadIdx.x;
    int lane = tid & 31;
    int w    = tid >> 5;
    int lg = lane >> 2;
    int lq = lane & 3;

    int bh = blockIdx.y;
    int b = bh >> 4;
    int h = bh & 15;
    int s0 = blockIdx.x * 64;

    const float* Qbase = QKV + (size_t)(b * SS) * N3 + h * DKK;
    const float* Kbase = Qbase + 1024;
    const float* Vbase = Qbase + 2048;

    // load Q tile (scaled by 1/8, tf32)
    #pragma unroll
    for (int L = 0; L < 8; L++) {
        int idx = tid + L * 128;
        int r  = idx >> 4;
        int c4 = (idx & 15) << 2;
        float4 v = *(const float4*)(Qbase + (size_t)(s0 + r) * N3 + c4);
        Qs[r * QS_STR + c4 + 0] = f2tf32(v.x * 0.125f);
        Qs[r * QS_STR + c4 + 1] = f2tf32(v.y * 0.125f);
        Qs[r * QS_STR + c4 + 2] = f2tf32(v.z * 0.125f);
        Qs[r * QS_STR + c4 + 3] = f2tf32(v.w * 0.125f);
    }

    float o[8][4];
    #pragma unroll
    for (int nt = 0; nt < 8; nt++)
        #pragma unroll
        for (int r = 0; r < 4; r++) o[nt][r] = 0.0f;
    float m_run[2] = {-1e30f, -1e30f};
    float l_run[2] = {0.0f, 0.0f};

    int rbase = w * 16;   // warp's q-row base within tile

    for (int kt = 0; kt < SS; kt += 64) {
        // load K and V tiles
        #pragma unroll
        for (int L = 0; L < 8; L++) {
            int idx = tid + L * 128;
            int r  = idx >> 4;
            int c4 = (idx & 15) << 2;
            float4 kv = *(const float4*)(Kbase + (size_t)(kt + r) * N3 + c4);
            Ks[r * QS_STR + c4 + 0] = f2tf32(kv.x);
            Ks[r * QS_STR + c4 + 1] = f2tf32(kv.y);
            Ks[r * QS_STR + c4 + 2] = f2tf32(kv.z);
            Ks[r * QS_STR + c4 + 3] = f2tf32(kv.w);
            float4 vv = *(const float4*)(Vbase + (size_t)(kt + r) * N3 + c4);
            Vs[r * QS_STR + c4 + 0] = f2tf32(vv.x);
            Vs[r * QS_STR + c4 + 1] = f2tf32(vv.y);
            Vs[r * QS_STR + c4 + 2] = f2tf32(vv.z);
            Vs[r * QS_STR + c4 + 3] = f2tf32(vv.w);
        }
        __syncthreads();

        // S = Q * K^T : m16 x n64, contraction over dk=64
        float s[8][4];
        #pragma unroll
        for (int nt = 0; nt < 8; nt++)
            #pragma unroll
            for (int r = 0; r < 4; r++) s[nt][r] = 0.0f;

        #pragma unroll
        for (int ks = 0; ks < 8; ks++) {
            int k0 = ks * 8;
            unsigned a0 = Qs[(rbase + lg) * QS_STR + k0 + lq];
            unsigned a1 = Qs[(rbase + 8 + lg) * QS_STR + k0 + lq];
            unsigned a2 = Qs[(rbase + lg) * QS_STR + k0 + 4 + lq];
            unsigned a3 = Qs[(rbase + 8 + lg) * QS_STR + k0 + 4 + lq];
            #pragma unroll
            for (int nt = 0; nt < 8; nt++) {
                // B[k=dk][n=t] = K[t][dk]
                unsigned b0 = Ks[(nt * 8 + lg) * QS_STR + k0 + lq];
                unsigned b1 = Ks[(nt * 8 + lg) * QS_STR + k0 + 4 + lq];
                mma_tf32(s[nt][0], s[nt][1], s[nt][2], s[nt][3], a0, a1, a2, a3, b0, b1);
            }
        }

        // online softmax: rows rbase+lg (regs 0,1) and rbase+8+lg (regs 2,3)
        float mloc0 = -1e30f, mloc1 = -1e30f;
        #pragma unroll
        for (int nt = 0; nt < 8; nt++) {
            mloc0 = fmaxf(mloc0, fmaxf(s[nt][0], s[nt][1]));
            mloc1 = fmaxf(mloc1, fmaxf(s[nt][2], s[nt][3]));
        }
        #pragma unroll
        for (int off = 1; off <= 2; off <<= 1) {
            mloc0 = fmaxf(mloc0, __shfl_xor_sync(0xffffffffu, mloc0, off));
            mloc1 = fmaxf(mloc1, __shfl_xor_sync(0xffffffffu, mloc1, off));
        }
        float mnew0 = fmaxf(m_run[0], mloc0);
        float mnew1 = fmaxf(m_run[1], mloc1);
        float alpha0 = __expf(m_run[0] - mnew0);
        float alpha1 = __expf(m_run[1] - mnew1);

        float rs0 = 0.0f, rs1 = 0.0f;
        #pragma unroll
        for (int nt = 0; nt < 8; nt++) {
            s[nt][0] = __expf(s[nt][0] - mnew0);
            s[nt][1] = __expf(s[nt][1] - mnew0);
            s[nt][2] = __expf(s[nt][2] - mnew1);
            s[nt][3] = __expf(s[nt][3] - mnew1);
            rs0 += s[nt][0] + s[nt][1];
            rs1 += s[nt][2] + s[nt][3];
        }
        #pragma unroll
        for (int off = 1; off <= 2; off <<= 1) {
            rs0 += __shfl_xor_sync(0xffffffffu, rs0, off);
            rs1 += __shfl_xor_sync(0xffffffffu, rs1, off);
        }
        l_run[0] = l_run[0] * alpha0 + rs0;
        l_run[1] = l_run[1] * alpha1 + rs1;
        m_run[0] = mnew0;
        m_run[1] = mnew1;
        #pragma unroll
        for (int nt = 0; nt < 8; nt++) {
            o[nt][0] *= alpha0; o[nt][1] *= alpha0;
            o[nt][2] *= alpha1; o[nt][3] *= alpha1;
        }

        // stage P into per-warp smem region (rows rbase..rbase+15)
        #pragma unroll
        for (int nt = 0; nt < 8; nt++) {
            int col = nt * 8 + 2 * lq;
            Ps[(rbase + lg) * QS_STR + col]     = f2tf32(s[nt][0]);
            Ps[(rbase + lg) * QS_STR + col + 1] = f2tf32(s[nt][1]);
            Ps[(rbase + 8 + lg) * QS_STR + col]     = f2tf32(s[nt][2]);
            Ps[(rbase + 8 + lg) * QS_STR + col + 1] = f2tf32(s[nt][3]);
        }
        __syncwarp();

        // O += P * V : contraction over t=64, n = dk 64
        #pragma unroll
        for (int ks = 0; ks < 8; ks++) {
            int k0 = ks * 8;
            unsigned a0 = Ps[(rbase + lg) * QS_STR + k0 + lq];
            unsigned a1 = Ps[(rbase + 8 + lg) * QS_STR + k0 + lq];
            unsigned a2 = Ps[(rbase + lg) * QS_STR + k0 + 4 + lq];
            unsigned a3 = Ps[(rbase + 8 + lg) * QS_STR + k0 + 4 + lq];
            #pragma unroll
            for (int nt = 0; nt < 8; nt++) {
                unsigned b0 = Vs[(k0 + lq) * QS_STR + nt * 8 + lg];
                unsigned b1 = Vs[(k0 + 4 + lq) * QS_STR + nt * 8 + lg];
                mma_tf32(o[nt][0], o[nt][1], o[nt][2], o[nt][3], a0, a1, a2, a3, b0, b1);
            }
        }
        __syncthreads();   // protect Ks/Vs before next tile load
    }

    // epilogue: normalize + write concat [B,S,H*DK]
    float inv0 = 1.0f / l_run[0];
    float inv1 = 1.0f / l_run[1];
    int row0 = s0 + rbase + lg;
    #pragma unroll
    for (int nt = 0; nt < 8; nt++) {
        int col = h * DKK + nt * 8 + 2 * lq;
        float2 v0 = make_float2(o[nt][0] * inv0, o[nt][1] * inv0);
        float2 v1 = make_float2(o[nt][2] * inv1, o[nt][3] * inv1);
        *(float2*)(cat + (size_t)(b * SS + row0) * DOUTT + col) = v0;
        *(float2*)(cat + (size_t)(b * SS + row0 + 8) * DOUTT + col) = v1;
    }
}

// ============================================================
// launch
// ============================================================
extern "C" void kernel_launch(void* const* d_in, const int* in_sizes, int n_in,
                              void* d_out, int out_size) {
    const float* x  = (const float*)d_in[0];
    const float* Wq = (const float*)d_in[1];
    const float* bq = (const float*)d_in[2];
    const float* Wk = (const float*)d_in[3];
    const float* bk = (const float*)d_in[4];
    const float* Wv = (const float*)d_in[5];
    const float* bv = (const float*)d_in[6];
    const float* Wo = (const float*)d_in[7];
    const float* bo = (const float*)d_in[8];
    float* out = (float*)d_out;

    float *pWqkv, *pbqkv, *pQKV, *pcat;
    cudaGetSymbolAddress((void**)&pWqkv, g_Wqkv);
    cudaGetSymbolAddress((void**)&pbqkv, g_bqkv);
    cudaGetSymbolAddress((void**)&pQKV,  g_QKV);
    cudaGetSymbolAddress((void**)&pcat,  g_cat);

    {
        int total = 3 * DD * HH * DKK;
        pack_weights_kernel<<<(total + 255) / 256, 256>>>(Wq, bq, Wk, bk, Wv, bv);
    }
    {
        dim3 grid(N3 / 128, MM / 128);
        gemm_tf32_kernel<<<grid, 256>>>(x, pWqkv, pbqkv, pQKV, MM, N3, DD);
    }
    {
        cudaFuncSetAttribute(attn_tc_kernel, cudaFuncAttributeMaxDynamicSharedMemorySize,
                             ATT_SMEM_BYTES);
        dim3 grid(SS / 64, BB * HH);
        attn_tc_kernel<<<grid, 128, ATT_SMEM_BYTES>>>(pQKV, pcat);
    }
    {
        dim3 grid(DOUTT / 128, MM / 128);
        gemm_tf32_kernel<<<grid, 256>>>(pcat, Wo, bo, out, MM, DOUTT, DD);
    }
}

// round 3
// speedup vs baseline: 3.3821x; 1.3428x over previous
#include <cuda_runtime.h>
#include <math.h>
#include <stdint.h>

#define BB   4
#define SS   2048
#define DD   1024
#define HH   16
#define DKK  64
#define DOUTT 1024
#define MM   (BB*SS)          // 8192
#define N3   (3*HH*DKK)       // 3072

// -------- scratch --------
__device__ float g_Wqkv[DD * N3];            // tf32-rounded packed weights
__device__ float g_bqkv[N3];
__device__ float g_Wo[DD * DOUTT];           // tf32-rounded Wo
__device__ float g_xr[(size_t)MM * DD];      // tf32-rounded x
__device__ float g_QKV[(size_t)MM * N3];     // tf32-rounded QKV
__device__ float g_cat[(size_t)MM * DOUTT];  // tf32-rounded concat

__device__ __forceinline__ unsigned f2tf32(float x) {
    unsigned r;
    asm("cvt.rna.tf32.f32 %0, %1;" : "=r"(r) : "f"(x));
    return r;
}

__device__ __forceinline__ void mma_tf32(float& c0, float& c1, float& c2, float& c3,
                                         unsigned a0, unsigned a1, unsigned a2, unsigned a3,
                                         unsigned b0, unsigned b1) {
    asm volatile(
        "mma.sync.aligned.m16n8k8.row.col.f32.tf32.tf32.f32 "
        "{%0,%1,%2,%3}, {%4,%5,%6,%7}, {%8,%9}, {%0,%1,%2,%3};\n"
        : "+f"(c0), "+f"(c1), "+f"(c2), "+f"(c3)
        : "r"(a0), "r"(a1), "r"(a2), "r"(a3), "r"(b0), "r"(b1));
}

__device__ __forceinline__ void cp16(unsigned* smem_ptr, const float* gmem_ptr) {
    unsigned dst = (unsigned)__cvta_generic_to_shared(smem_ptr);
    asm volatile("cp.async.cg.shared.global [%0], [%1], 16;\n" :: "r"(dst), "l"(gmem_ptr));
}
#define CP_COMMIT() asm volatile("cp.async.commit_group;\n" ::: "memory")
#define CP_WAIT(n)  asm volatile("cp.async.wait_group %0;\n" :: "n"(n) : "memory")

// ============================================================
// Kernel 0: round x to tf32 grid
// ============================================================
__global__ void round_x_kernel(const float* __restrict__ x) {
    size_t i = (size_t)(blockIdx.x * blockDim.x + threadIdx.x) * 4;
    if (i < (size_t)MM * DD) {
        float4 v = *(const float4*)(x + i);
        float4 o;
        o.x = __uint_as_float(f2tf32(v.x));
        o.y = __uint_as_float(f2tf32(v.y));
        o.z = __uint_as_float(f2tf32(v.z));
        o.w = __uint_as_float(f2tf32(v.w));
        *(float4*)(g_xr + i) = o;
    }
}

// ============================================================
// Kernel 1: pack+round weights
// ============================================================
__global__ void pack_weights_kernel(const float* __restrict__ Wq,
                                    const float* __restrict__ bq,
                                    const float* __restrict__ Wk,
                                    const float* __restrict__ bk,
                                    const float* __restrict__ Wv,
                                    const float* __restrict__ bv,
                                    const float* __restrict__ Wo) {
    int idx = blockIdx.x * blockDim.x + threadIdx.x;
    const int per = DD * HH * DKK;
    if (idx < 3 * per) {
        int which = idx / per;
        int rem   = idx % per;
        int d = rem >> 10;
        int c = rem & 1023;
        int h = c >> 6;
        int k = c & 63;
        const float* W = (which == 0) ? Wq : (which == 1) ? Wk : Wv;
        g_Wqkv[(size_t)d * N3 + which * 1024 + c] =
            __uint_as_float(f2tf32(W[h * (DD * DKK) + d * DKK + k]));
    }
    if (idx < N3) {
        int which = idx >> 10;
        int c = idx & 1023;
        const float* bsrc = (which == 0) ? bq : (which == 1) ? bk : bv;
        g_bqkv[idx] = bsrc[c];
    }
    if (idx < DD * DOUTT) {
        g_Wo[idx] = __uint_as_float(f2tf32(Wo[idx]));
    }
}

// ============================================================
// Kernel 2: TF32 GEMM, cp.async double-buffered.
// Inputs MUST be pre-rounded to tf32 grid. C = A*B + bias.
// block 256 (8 warps), tile 128x128, BK=16, warp 32x64.
// ============================================================
#define GA_STR 20    // 20 mod 32 -> a-frag conflict-free
#define GB_STR 136   // 136 mod 32 = 8 -> b-frag conflict-free

__global__ __launch_bounds__(256) void gemm_tf32_db(
    const float* __restrict__ A, const float* __restrict__ Bw,
    const float* __restrict__ bias, float* __restrict__ C,
    int M, int N, int K, int round_out)
{
    __shared__ unsigned As[2][128 * GA_STR];
    __shared__ unsigned Bs[2][16 * GB_STR];

    int tid  = threadIdx.x;
    int lane = tid & 31;
    int w    = tid >> 5;
    int warp_m = w >> 1;
    int warp_n = w & 1;
    int lg = lane >> 2;
    int lq = lane & 3;

    const float* Aptr = A + (size_t)(blockIdx.y * 128) * K;
    const float* Bptr = Bw + blockIdx.x * 128;

    // precompute this thread's cp.async targets
    int ar = tid >> 2;                 // A row for L=0 (L=1: +64)
    int akk = (tid & 3) << 2;
    int bkk = tid >> 5;                // B k for L=0 (L=1: +8)
    int bn4 = (tid & 31) << 2;

    // prologue: stage 0
    {
        cp16(&As[0][ar * GA_STR + akk],        Aptr + (size_t)ar * K + akk);
        cp16(&As[0][(ar + 64) * GA_STR + akk], Aptr + (size_t)(ar + 64) * K + akk);
        cp16(&Bs[0][bkk * GB_STR + bn4],       Bptr + (size_t)bkk * N + bn4);
        cp16(&Bs[0][(bkk + 8) * GB_STR + bn4], Bptr + (size_t)(bkk + 8) * N + bn4);
    }
    CP_COMMIT();

    float acc[2][8][4];
    #pragma unroll
    for (int mt = 0; mt < 2; mt++)
        #pragma unroll
        for (int nt = 0; nt < 8; nt++)
            #pragma unroll
            for (int r = 0; r < 4; r++) acc[mt][nt][r] = 0.0f;

    int ntk = K >> 4;
    for (int t = 0; t < ntk; t++) {
        int st = t & 1;
        if (t + 1 < ntk) {
            int kt = (t + 1) << 4;
            int ns = st ^ 1;
            cp16(&As[ns][ar * GA_STR + akk],        Aptr + (size_t)ar * K + kt + akk);
            cp16(&As[ns][(ar + 64) * GA_STR + akk], Aptr + (size_t)(ar + 64) * K + kt + akk);
            cp16(&Bs[ns][bkk * GB_STR + bn4],       Bptr + (size_t)(kt + bkk) * N + bn4);
            cp16(&Bs[ns][(bkk + 8) * GB_STR + bn4], Bptr + (size_t)(kt + bkk + 8) * N + bn4);
            CP_COMMIT();
            CP_WAIT(1);
        } else {
            CP_WAIT(0);
        }
        __syncthreads();

        const unsigned* Asl = As[st];
        const unsigned* Bsl = Bs[st];
        #pragma unroll
        for (int ks = 0; ks < 2; ks++) {
            int k0 = ks * 8;
            unsigned af[2][4];
            #pragma unroll
            for (int mt = 0; mt < 2; mt++) {
                int mb = warp_m * 32 + mt * 16;
                af[mt][0] = Asl[(mb + lg) * GA_STR + k0 + lq];
                af[mt][1] = Asl[(mb + 8 + lg) * GA_STR + k0 + lq];
                af[mt][2] = Asl[(mb + lg) * GA_STR + k0 + 4 + lq];
                af[mt][3] = Asl[(mb + 8 + lg) * GA_STR + k0 + 4 + lq];
            }
            #pragma unroll
            for (int nt = 0; nt < 8; nt++) {
                int nb = warp_n * 64 + nt * 8;
                unsigned b0 = Bsl[(k0 + lq) * GB_STR + nb + lg];
                unsigned b1 = Bsl[(k0 + 4 + lq) * GB_STR + nb + lg];
                #pragma unroll
                for (int mt = 0; mt < 2; mt++)
                    mma_tf32(acc[mt][nt][0], acc[mt][nt][1], acc[mt][nt][2], acc[mt][nt][3],
                             af[mt][0], af[mt][1], af[mt][2], af[mt][3], b0, b1);
            }
        }
        __syncthreads();
    }

    #pragma unroll
    for (int mt = 0; mt < 2; mt++) {
        int row0 = blockIdx.y * 128 + warp_m * 32 + mt * 16 + lg;
        #pragma unroll
        for (int nt = 0; nt < 8; nt++) {
            int col = blockIdx.x * 128 + warp_n * 64 + nt * 8 + 2 * lq;
            float b0 = bias[col], b1 = bias[col + 1];
            float r00 = acc[mt][nt][0] + b0, r01 = acc[mt][nt][1] + b1;
            float r10 = acc[mt][nt][2] + b0, r11 = acc[mt][nt][3] + b1;
            if (round_out) {
                r00 = __uint_as_float(f2tf32(r00));
                r01 = __uint_as_float(f2tf32(r01));
                r10 = __uint_as_float(f2tf32(r10));
                r11 = __uint_as_float(f2tf32(r11));
            }
            *(float2*)(C + (size_t)row0 * N + col) = make_float2(r00, r01);
            *(float2*)(C + (size_t)(row0 + 8) * N + col) = make_float2(r10, r11);
        }
    }
}

// ============================================================
// Kernel 3: flash attention v2.
// block 256 (8 warps), Q tile 256 rows (warp w: rows w*32..w*32+31),
// K/V tiles of 64 keys, cp.async double-buffered, no cvt except P.
// ============================================================
#define AQ_STR 68    // 68 mod 32 = 4 -> row-major frag reads conflict-free
#define ATT_SMEM_WORDS (256*AQ_STR + 2*64*AQ_STR + 2*64*AQ_STR + 256*AQ_STR)

__global__ __launch_bounds__(256) void attn_tc2(const float* __restrict__ QKV,
                                                float* __restrict__ cat)
{
    extern __shared__ unsigned sm[];
    unsigned* Qs = sm;                        // [256][68]
    unsigned* Ks = sm + 256 * AQ_STR;         // [2][64][68]
    unsigned* Vs = Ks + 2 * 64 * AQ_STR;      // [2][64][68]
    unsigned* Ps = Vs + 2 * 64 * AQ_STR;      // [256][68]

    int tid  = threadIdx.x;
    int lane = tid & 31;
    int w    = tid >> 5;
    int lg = lane >> 2;
    int lq = lane & 3;
    int rbase = w * 32;

    int bh = blockIdx.y;
    int b = bh >> 4;
    int h = bh & 15;
    int s0 = blockIdx.x * 256;

    const float* Qbase = QKV + (size_t)(b * SS) * N3 + h * DKK;
    const float* Kbase = Qbase + 1024;
    const float* Vbase = Qbase + 2048;

    // cp.async target indices for K/V tiles (64 rows x 64 cols)
    int kvr = tid >> 4;                 // row for L=0 (L adds 16)
    int kvc4 = (tid & 15) << 2;

    // prologue: prefetch KV tile 0 into stage 0
    #pragma unroll
    for (int L = 0; L < 4; L++) {
        int r = kvr + L * 16;
        cp16(&Ks[r * AQ_STR + kvc4], Kbase + (size_t)r * N3 + kvc4);
        cp16(&Vs[r * AQ_STR + kvc4], Vbase + (size_t)r * N3 + kvc4);
    }
    CP_COMMIT();

    // load Q tile (256 x 64), scale by 0.125 (exact, stays on tf32 grid)
    #pragma unroll
    for (int L = 0; L < 16; L++) {
        int idx = tid + L * 256;
        int r  = idx >> 4;
        int c4 = (idx & 15) << 2;
        float4 v = *(const float4*)(Qbase + (size_t)(s0 + r) * N3 + c4);
        Qs[r * AQ_STR + c4 + 0] = __float_as_uint(v.x * 0.125f);
        Qs[r * AQ_STR + c4 + 1] = __float_as_uint(v.y * 0.125f);
        Qs[r * AQ_STR + c4 + 2] = __float_as_uint(v.z * 0.125f);
        Qs[r * AQ_STR + c4 + 3] = __float_as_uint(v.w * 0.125f);
    }

    float o[2][8][4];
    #pragma unroll
    for (int mt = 0; mt < 2; mt++)
        #pragma unroll
        for (int nt = 0; nt < 8; nt++)
            #pragma unroll
            for (int r = 0; r < 4; r++) o[mt][nt][r] = 0.0f;
    float mrun[2][2] = {{-1e30f, -1e30f}, {-1e30f, -1e30f}};
    float lrun[2][2] = {{0.0f, 0.0f}, {0.0f, 0.0f}};

    const int NT = SS / 64;   // 32 key tiles
    for (int t = 0; t < NT; t++) {
        int st = t & 1;
        if (t + 1 < NT) {
            int kt = (t + 1) * 64;
            unsigned* Kn = Ks + (st ^ 1) * 64 * AQ_STR;
            unsigned* Vn = Vs + (st ^ 1) * 64 * AQ_STR;
            #pragma unroll
            for (int L = 0; L < 4; L++) {
                int r = kvr + L * 16;
                cp16(&Kn[r * AQ_STR + kvc4], Kbase + (size_t)(kt + r) * N3 + kvc4);
                cp16(&Vn[r * AQ_STR + kvc4], Vbase + (size_t)(kt + r) * N3 + kvc4);
            }
            CP_COMMIT();
            CP_WAIT(1);
        } else {
            CP_WAIT(0);
        }
        __syncthreads();

        const unsigned* K_ = Ks + st * 64 * AQ_STR;
        const unsigned* V_ = Vs + st * 64 * AQ_STR;

        // ---- S = Q * K^T (warp: 32 rows x 64 keys) ----
        float s[2][8][4];
        #pragma unroll
        for (int mt = 0; mt < 2; mt++)
            #pragma unroll
            for (int nt = 0; nt < 8; nt++)
                #pragma unroll
                for (int r = 0; r < 4; r++) s[mt][nt][r] = 0.0f;

        #pragma unroll
        for (int ks = 0; ks < 8; ks++) {
            int k0 = ks * 8;
            unsigned af[2][4];
            #pragma unroll
            for (int mt = 0; mt < 2; mt++) {
                int mb = rbase + mt * 16;
                af[mt][0] = Qs[(mb + lg) * AQ_STR + k0 + lq];
                af[mt][1] = Qs[(mb + 8 + lg) * AQ_STR + k0 + lq];
                af[mt][2] = Qs[(mb + lg) * AQ_STR + k0 + 4 + lq];
                af[mt][3] = Qs[(mb + 8 + lg) * AQ_STR + k0 + 4 + lq];
            }
            #pragma unroll
            for (int nt = 0; nt < 8; nt++) {
                unsigned b0 = K_[(nt * 8 + lg) * AQ_STR + k0 + lq];
                unsigned b1 = K_[(nt * 8 + lg) * AQ_STR + k0 + 4 + lq];
                #pragma unroll
                for (int mt = 0; mt < 2; mt++)
                    mma_tf32(s[mt][nt][0], s[mt][nt][1], s[mt][nt][2], s[mt][nt][3],
                             af[mt][0], af[mt][1], af[mt][2], af[mt][3], b0, b1);
            }
        }

        // ---- online softmax (rows lg and lg+8 per mt) + stage P ----
        #pragma unroll
        for (int mt = 0; mt < 2; mt++) {
            float mloc0 = -1e30f, mloc1 = -1e30f;
            #pragma unroll
            for (int nt = 0; nt < 8; nt++) {
                mloc0 = fmaxf(mloc0, fmaxf(s[mt][nt][0], s[mt][nt][1]));
                mloc1 = fmaxf(mloc1, fmaxf(s[mt][nt][2], s[mt][nt][3]));
            }
            #pragma unroll
            for (int off = 1; off <= 2; off <<= 1) {
                mloc0 = fmaxf(mloc0, __shfl_xor_sync(0xffffffffu, mloc0, off));
                mloc1 = fmaxf(mloc1, __shfl_xor_sync(0xffffffffu, mloc1, off));
            }
            float mnew0 = fmaxf(mrun[mt][0], mloc0);
            float mnew1 = fmaxf(mrun[mt][1], mloc1);
            float alpha0 = __expf(mrun[mt][0] - mnew0);
            float alpha1 = __expf(mrun[mt][1] - mnew1);

            float rs0 = 0.0f, rs1 = 0.0f;
            #pragma unroll
            for (int nt = 0; nt < 8; nt++) {
                s[mt][nt][0] = __expf(s[mt][nt][0] - mnew0);
                s[mt][nt][1] = __expf(s[mt][nt][1] - mnew0);
                s[mt][nt][2] = __expf(s[mt][nt][2] - mnew1);
                s[mt][nt][3] = __expf(s[mt][nt][3] - mnew1);
                rs0 += s[mt][nt][0] + s[mt][nt][1];
                rs1 += s[mt][nt][2] + s[mt][nt][3];
            }
            #pragma unroll
            for (int off = 1; off <= 2; off <<= 1) {
                rs0 += __shfl_xor_sync(0xffffffffu, rs0, off);
                rs1 += __shfl_xor_sync(0xffffffffu, rs1, off);
            }
            lrun[mt][0] = lrun[mt][0] * alpha0 + rs0;
            lrun[mt][1] = lrun[mt][1] * alpha1 + rs1;
            mrun[mt][0] = mnew0;
            mrun[mt][1] = mnew1;
            #pragma unroll
            for (int nt = 0; nt < 8; nt++) {
                o[mt][nt][0] *= alpha0; o[mt][nt][1] *= alpha0;
                o[mt][nt][2] *= alpha1; o[mt][nt][3] *= alpha1;
            }
            // stage P rows for this mt
            int mb = rbase + mt * 16;
            #pragma unroll
            for (int nt = 0; nt < 8; nt++) {
                int col = nt * 8 + 2 * lq;
                Ps[(mb + lg) * AQ_STR + col]         = f2tf32(s[mt][nt][0]);
                Ps[(mb + lg) * AQ_STR + col + 1]     = f2tf32(s[mt][nt][1]);
                Ps[(mb + 8 + lg) * AQ_STR + col]     = f2tf32(s[mt][nt][2]);
                Ps[(mb + 8 + lg) * AQ_STR + col + 1] = f2tf32(s[mt][nt][3]);
            }
        }
        __syncwarp();

        // ---- O += P * V ----
        #pragma unroll
        for (int ks = 0; ks < 8; ks++) {
            int k0 = ks * 8;
            unsigned af[2][4];
            #pragma unroll
            for (int mt = 0; mt < 2; mt++) {
                int mb = rbase + mt * 16;
                af[mt][0] = Ps[(mb + lg) * AQ_STR + k0 + lq];
                af[mt][1] = Ps[(mb + 8 + lg) * AQ_STR + k0 + lq];
                af[mt][2] = Ps[(mb + lg) * AQ_STR + k0 + 4 + lq];
                af[mt][3] = Ps[(mb + 8 + lg) * AQ_STR + k0 + 4 + lq];
            }
            #pragma unroll
            for (int nt = 0; nt < 8; nt++) {
                unsigned b0 = V_[(k0 + lq) * AQ_STR + nt * 8 + lg];
                unsigned b1 = V_[(k0 + 4 + lq) * AQ_STR + nt * 8 + lg];
                #pragma unroll
                for (int mt = 0; mt < 2; mt++)
                    mma_tf32(o[mt][nt][0], o[mt][nt][1], o[mt][nt][2], o[mt][nt][3],
                             af[mt][0], af[mt][1], af[mt][2], af[mt][3], b0, b1);
            }
        }
        __syncthreads();   // stage reuse + Ps reuse protection
    }

    // epilogue: normalize, round to tf32, write concat [B,S,H*DK]
    #pragma unroll
    for (int mt = 0; mt < 2; mt++) {
        float inv0 = 1.0f / lrun[mt][0];
        float inv1 = 1.0f / lrun[mt][1];
        int row = s0 + rbase + mt * 16 + lg;
        #pragma unroll
        for (int nt = 0; nt < 8; nt++) {
            int col = h * DKK + nt * 8 + 2 * lq;
            float2 v0 = make_float2(__uint_as_float(f2tf32(o[mt][nt][0] * inv0)),
                                    __uint_as_float(f2tf32(o[mt][nt][1] * inv0)));
            float2 v1 = make_float2(__uint_as_float(f2tf32(o[mt][nt][2] * inv1)),
                                    __uint_as_float(f2tf32(o[mt][nt][3] * inv1)));
            *(float2*)(cat + (size_t)(b * SS + row) * DOUTT + col) = v0;
            *(float2*)(cat + (size_t)(b * SS + row + 8) * DOUTT + col) = v1;
        }
    }
}

// ============================================================
// launch
// ============================================================
extern "C" void kernel_launch(void* const* d_in, const int* in_sizes, int n_in,
                              void* d_out, int out_size) {
    const float* x  = (const float*)d_in[0];
    const float* Wq = (const float*)d_in[1];
    const float* bq = (const float*)d_in[2];
    const float* Wk = (const float*)d_in[3];
    const float* bk = (const float*)d_in[4];
    const float* Wv = (const float*)d_in[5];
    const float* bv = (const float*)d_in[6];
    const float* Wo = (const float*)d_in[7];
    const float* bo = (const float*)d_in[8];
    float* out = (float*)d_out;

    float *pWqkv, *pbqkv, *pWo, *pxr, *pQKV, *pcat;
    cudaGetSymbolAddress((void**)&pWqkv, g_Wqkv);
    cudaGetSymbolAddress((void**)&pbqkv, g_bqkv);
    cudaGetSymbolAddress((void**)&pWo,   g_Wo);
    cudaGetSymbolAddress((void**)&pxr,   g_xr);
    cudaGetSymbolAddress((void**)&pQKV,  g_QKV);
    cudaGetSymbolAddress((void**)&pcat,  g_cat);

    {
        int n4 = MM * DD / 4;
        round_x_kernel<<<(n4 + 255) / 256, 256>>>(x);
    }
    {
        int total = 3 * DD * HH * DKK;
        pack_weights_kernel<<<(total + 255) / 256, 256>>>(Wq, bq, Wk, bk, Wv, bv, Wo);
    }
    {
        dim3 grid(N3 / 128, MM / 128);
        gemm_tf32_db<<<grid, 256>>>(pxr, pWqkv, pbqkv, pQKV, MM, N3, DD, 1);
    }
    {
        cudaFuncSetAttribute(attn_tc2, cudaFuncAttributeMaxDynamicSharedMemorySize,
                             ATT_SMEM_WORDS * (int)sizeof(unsigned));
        dim3 grid(SS / 256, BB * HH);
        attn_tc2<<<grid, 256, ATT_SMEM_WORDS * sizeof(unsigned)>>>(pQKV, pcat);
    }
    {
        dim3 grid(DOUTT / 128, MM / 128);
        gemm_tf32_db<<<grid, 256>>>(pcat, pWo, bo, out, MM, DOUTT, DD, 0);
    }
}

// round 4
// speedup vs baseline: 3.4225x; 1.0119x over previous
#include <cuda_runtime.h>
#include <math.h>
#include <stdint.h>

#define BB   4
#define SS   2048
#define DD   1024
#define HH   16
#define DKK  64
#define DOUTT 1024
#define MM   (BB*SS)
#define N3   (3*HH*DKK)

// -------- scratch --------
__device__ float g_Wqkv[DD * N3];
__device__ float g_bqkv[N3];
__device__ float g_Wo[DD * DOUTT];
__device__ float g_xr[(size_t)MM * DD];
__device__ float g_QKV[(size_t)MM * N3];
__device__ float g_cat[(size_t)MM * DOUTT];

__device__ __forceinline__ unsigned f2tf32(float x) {
    unsigned r;
    asm("cvt.rna.tf32.f32 %0, %1;" : "=r"(r) : "f"(x));
    return r;
}

__device__ __forceinline__ void mma_tf32(float& c0, float& c1, float& c2, float& c3,
                                         unsigned a0, unsigned a1, unsigned a2, unsigned a3,
                                         unsigned b0, unsigned b1) {
    asm volatile(
        "mma.sync.aligned.m16n8k8.row.col.f32.tf32.tf32.f32 "
        "{%0,%1,%2,%3}, {%4,%5,%6,%7}, {%8,%9}, {%0,%1,%2,%3};\n"
        : "+f"(c0), "+f"(c1), "+f"(c2), "+f"(c3)
        : "r"(a0), "r"(a1), "r"(a2), "r"(a3), "r"(b0), "r"(b1));
}

__device__ __forceinline__ void cp16(unsigned* smem_ptr, const float* gmem_ptr) {
    unsigned dst = (unsigned)__cvta_generic_to_shared(smem_ptr);
    asm volatile("cp.async.cg.shared.global [%0], [%1], 16;\n" :: "r"(dst), "l"(gmem_ptr));
}
#define CP_COMMIT() asm volatile("cp.async.commit_group;\n" ::: "memory")
#define CP_WAIT(n)  asm volatile("cp.async.wait_group %0;\n" :: "n"(n) : "memory")

// ============================================================
// Kernel 0: round x to tf32 grid
// ============================================================
__global__ void round_x_kernel(const float* __restrict__ x) {
    size_t i = (size_t)(blockIdx.x * blockDim.x + threadIdx.x) * 4;
    if (i < (size_t)MM * DD) {
        float4 v = *(const float4*)(x + i);
        float4 o;
        o.x = __uint_as_float(f2tf32(v.x));
        o.y = __uint_as_float(f2tf32(v.y));
        o.z = __uint_as_float(f2tf32(v.z));
        o.w = __uint_as_float(f2tf32(v.w));
        *(float4*)(g_xr + i) = o;
    }
}

// ============================================================
// Kernel 1: pack+round weights
// ============================================================
__global__ void pack_weights_kernel(const float* __restrict__ Wq,
                                    const float* __restrict__ bq,
                                    const float* __restrict__ Wk,
                                    const float* __restrict__ bk,
                                    const float* __restrict__ Wv,
                                    const float* __restrict__ bv,
                                    const float* __restrict__ Wo) {
    int idx = blockIdx.x * blockDim.x + threadIdx.x;
    const int per = DD * HH * DKK;
    if (idx < 3 * per) {
        int which = idx / per;
        int rem   = idx % per;
        int d = rem >> 10;
        int c = rem & 1023;
        int h = c >> 6;
        int k = c & 63;
        const float* W = (which == 0) ? Wq : (which == 1) ? Wk : Wv;
        g_Wqkv[(size_t)d * N3 + which * 1024 + c] =
            __uint_as_float(f2tf32(W[h * (DD * DKK) + d * DKK + k]));
    }
    if (idx < N3) {
        int which = idx >> 10;
        int c = idx & 1023;
        const float* bsrc = (which == 0) ? bq : (which == 1) ? bk : bv;
        g_bqkv[idx] = bsrc[c];
    }
    if (idx < DD * DOUTT) {
        g_Wo[idx] = __uint_as_float(f2tf32(Wo[idx]));
    }
}

// ============================================================
// Kernel 2: TF32 GEMM, 4-stage cp.async pipeline (dynamic smem).
// block 256 (8 warps), tile 128x128, BK=16, warp 32x64.
// ============================================================
#define GA_STR 20
#define GB_STR 136
#define G_STAGE_A (128 * GA_STR)
#define G_STAGE_B (16 * GB_STR)
#define GEMM_SMEM_WORDS (4 * (G_STAGE_A + G_STAGE_B))   // 18944 words = 75776 B

__global__ __launch_bounds__(256, 2) void gemm_tf32_p4(
    const float* __restrict__ A, const float* __restrict__ Bw,
    const float* __restrict__ bias, float* __restrict__ C,
    int M, int N, int K, int round_out)
{
    extern __shared__ unsigned gsm[];
    unsigned* As = gsm;                    // [4][128*GA_STR]
    unsigned* Bs = gsm + 4 * G_STAGE_A;    // [4][16*GB_STR]

    int tid  = threadIdx.x;
    int lane = tid & 31;
    int w    = tid >> 5;
    int warp_m = w >> 1;
    int warp_n = w & 1;
    int lg = lane >> 2;
    int lq = lane & 3;

    const float* Aptr = A + (size_t)(blockIdx.y * 128) * K;
    const float* Bptr = Bw + blockIdx.x * 128;

    int ar  = tid >> 2;
    int akk = (tid & 3) << 2;
    int bkk = tid >> 5;
    int bn4 = (tid & 31) << 2;

    int ntk = K >> 4;

    // prologue: stages 0..2
    #pragma unroll
    for (int ps = 0; ps < 3; ps++) {
        int kt = ps << 4;
        unsigned* Asp = As + ps * G_STAGE_A;
        unsigned* Bsp = Bs + ps * G_STAGE_B;
        cp16(&Asp[ar * GA_STR + akk],        Aptr + (size_t)ar * K + kt + akk);
        cp16(&Asp[(ar + 64) * GA_STR + akk], Aptr + (size_t)(ar + 64) * K + kt + akk);
        cp16(&Bsp[bkk * GB_STR + bn4],       Bptr + (size_t)(kt + bkk) * N + bn4);
        cp16(&Bsp[(bkk + 8) * GB_STR + bn4], Bptr + (size_t)(kt + bkk + 8) * N + bn4);
        CP_COMMIT();
    }

    float acc[2][8][4];
    #pragma unroll
    for (int mt = 0; mt < 2; mt++)
        #pragma unroll
        for (int nt = 0; nt < 8; nt++)
            #pragma unroll
            for (int r = 0; r < 4; r++) acc[mt][nt][r] = 0.0f;

    for (int t = 0; t < ntk; t++) {
        if (t + 3 < ntk) {
            int kt = (t + 3) << 4;
            int ns = (t + 3) & 3;
            unsigned* Asp = As + ns * G_STAGE_A;
            unsigned* Bsp = Bs + ns * G_STAGE_B;
            cp16(&Asp[ar * GA_STR + akk],        Aptr + (size_t)ar * K + kt + akk);
            cp16(&Asp[(ar + 64) * GA_STR + akk], Aptr + (size_t)(ar + 64) * K + kt + akk);
            cp16(&Bsp[bkk * GB_STR + bn4],       Bptr + (size_t)(kt + bkk) * N + bn4);
            cp16(&Bsp[(bkk + 8) * GB_STR + bn4], Bptr + (size_t)(kt + bkk + 8) * N + bn4);
            CP_COMMIT();
        }
        CP_WAIT(2);
        __syncthreads();

        const unsigned* Asl = As + (t & 3) * G_STAGE_A;
        const unsigned* Bsl = Bs + (t & 3) * G_STAGE_B;
        #pragma unroll
        for (int ks = 0; ks < 2; ks++) {
            int k0 = ks * 8;
            unsigned af[2][4];
            #pragma unroll
            for (int mt = 0; mt < 2; mt++) {
                int mb = warp_m * 32 + mt * 16;
                af[mt][0] = Asl[(mb + lg) * GA_STR + k0 + lq];
                af[mt][1] = Asl[(mb + 8 + lg) * GA_STR + k0 + lq];
                af[mt][2] = Asl[(mb + lg) * GA_STR + k0 + 4 + lq];
                af[mt][3] = Asl[(mb + 8 + lg) * GA_STR + k0 + 4 + lq];
            }
            #pragma unroll
            for (int nt = 0; nt < 8; nt++) {
                int nb = warp_n * 64 + nt * 8;
                unsigned b0 = Bsl[(k0 + lq) * GB_STR + nb + lg];
                unsigned b1 = Bsl[(k0 + 4 + lq) * GB_STR + nb + lg];
                #pragma unroll
                for (int mt = 0; mt < 2; mt++)
                    mma_tf32(acc[mt][nt][0], acc[mt][nt][1], acc[mt][nt][2], acc[mt][nt][3],
                             af[mt][0], af[mt][1], af[mt][2], af[mt][3], b0, b1);
            }
        }
        __syncthreads();
    }

    #pragma unroll
    for (int mt = 0; mt < 2; mt++) {
        int row0 = blockIdx.y * 128 + warp_m * 32 + mt * 16 + lg;
        #pragma unroll
        for (int nt = 0; nt < 8; nt++) {
            int col = blockIdx.x * 128 + warp_n * 64 + nt * 8 + 2 * lq;
            float b0 = bias[col], b1 = bias[col + 1];
            float r00 = acc[mt][nt][0] + b0, r01 = acc[mt][nt][1] + b1;
            float r10 = acc[mt][nt][2] + b0, r11 = acc[mt][nt][3] + b1;
            if (round_out) {
                r00 = __uint_as_float(f2tf32(r00));
                r01 = __uint_as_float(f2tf32(r01));
                r10 = __uint_as_float(f2tf32(r10));
                r11 = __uint_as_float(f2tf32(r11));
            }
            *(float2*)(C + (size_t)row0 * N + col) = make_float2(r00, r01);
            *(float2*)(C + (size_t)(row0 + 8) * N + col) = make_float2(r10, r11);
        }
    }
}

// ============================================================
// Kernel 3: flash attention v3.
// block 256 (8 warps), Q tile 128 rows (warp w: rows w*16..w*16+15),
// K/V 64-key tiles double-buffered; P passed S->PV via register
// shuffles (no smem staging). 2 CTAs/SM.
// ============================================================
#define AQ_STR 68
#define ATT_SMEM_WORDS (128*AQ_STR + 2*64*AQ_STR + 2*64*AQ_STR)   // 26112 w = 104448 B

__global__ __launch_bounds__(256, 2) void attn_tc3(const float* __restrict__ QKV,
                                                   float* __restrict__ cat)
{
    extern __shared__ unsigned sm[];
    unsigned* Qs = sm;                    // [128][68]
    unsigned* Ks = sm + 128 * AQ_STR;     // [2][64][68]
    unsigned* Vs = Ks + 2 * 64 * AQ_STR;  // [2][64][68]

    int tid  = threadIdx.x;
    int lane = tid & 31;
    int w    = tid >> 5;
    int lg = lane >> 2;
    int lq = lane & 3;
    int rbase = w * 16;

    int bh = blockIdx.y;
    int b = bh >> 4;
    int h = bh & 15;
    int s0 = blockIdx.x * 128;

    const float* Qbase = QKV + (size_t)(b * SS) * N3 + h * DKK;
    const float* Kbase = Qbase + 1024;
    const float* Vbase = Qbase + 2048;

    int kvr  = tid >> 4;
    int kvc4 = (tid & 15) << 2;

    // prefetch KV tile 0
    #pragma unroll
    for (int L = 0; L < 4; L++) {
        int r = kvr + L * 16;
        cp16(&Ks[r * AQ_STR + kvc4], Kbase + (size_t)r * N3 + kvc4);
        cp16(&Vs[r * AQ_STR + kvc4], Vbase + (size_t)r * N3 + kvc4);
    }
    CP_COMMIT();

    // load Q tile (128x64), scale by (1/8)*log2(e), round to tf32
    const float QSC = 0.18033688011112042f;
    #pragma unroll
    for (int L = 0; L < 8; L++) {
        int idx = tid + L * 256;
        int r  = idx >> 4;
        int c4 = (idx & 15) << 2;
        float4 v = *(const float4*)(Qbase + (size_t)(s0 + r) * N3 + c4);
        Qs[r * AQ_STR + c4 + 0] = f2tf32(v.x * QSC);
        Qs[r * AQ_STR + c4 + 1] = f2tf32(v.y * QSC);
        Qs[r * AQ_STR + c4 + 2] = f2tf32(v.z * QSC);
        Qs[r * AQ_STR + c4 + 3] = f2tf32(v.w * QSC);
    }

    float o[8][4];
    #pragma unroll
    for (int nt = 0; nt < 8; nt++)
        #pragma unroll
        for (int r = 0; r < 4; r++) o[nt][r] = 0.0f;
    float m0 = -1e30f, m1 = -1e30f, l0 = 0.0f, l1 = 0.0f;

    // shuffle source lanes for S->A fragment conversion
    int L0 = (lane & ~3) | (lq >> 1);
    int L1 = L0 + 2;
    bool sel = (lq & 1);

    const int NT = SS / 64;
    for (int t = 0; t < NT; t++) {
        int st = t & 1;
        if (t + 1 < NT) {
            int kt = (t + 1) * 64;
            unsigned* Kn = Ks + (st ^ 1) * 64 * AQ_STR;
            unsigned* Vn = Vs + (st ^ 1) * 64 * AQ_STR;
            #pragma unroll
            for (int L = 0; L < 4; L++) {
                int r = kvr + L * 16;
                cp16(&Kn[r * AQ_STR + kvc4], Kbase + (size_t)(kt + r) * N3 + kvc4);
                cp16(&Vn[r * AQ_STR + kvc4], Vbase + (size_t)(kt + r) * N3 + kvc4);
            }
            CP_COMMIT();
            CP_WAIT(1);
        } else {
            CP_WAIT(0);
        }
        __syncthreads();

        const unsigned* K_ = Ks + st * 64 * AQ_STR;
        const unsigned* V_ = Vs + st * 64 * AQ_STR;

        // ---- S = Q*K^T (warp: 16 q-rows x 64 keys), base-2 scaled ----
        float s[8][4];
        #pragma unroll
        for (int nt = 0; nt < 8; nt++)
            #pragma unroll
            for (int r = 0; r < 4; r++) s[nt][r] = 0.0f;

        #pragma unroll
        for (int ks = 0; ks < 8; ks++) {
            int k0 = ks * 8;
            unsigned a0 = Qs[(rbase + lg) * AQ_STR + k0 + lq];
            unsigned a1 = Qs[(rbase + 8 + lg) * AQ_STR + k0 + lq];
            unsigned a2 = Qs[(rbase + lg) * AQ_STR + k0 + 4 + lq];
            unsigned a3 = Qs[(rbase + 8 + lg) * AQ_STR + k0 + 4 + lq];
            #pragma unroll
            for (int nt = 0; nt < 8; nt++) {
                unsigned b0 = K_[(nt * 8 + lg) * AQ_STR + k0 + lq];
                unsigned b1 = K_[(nt * 8 + lg) * AQ_STR + k0 + 4 + lq];
                mma_tf32(s[nt][0], s[nt][1], s[nt][2], s[nt][3], a0, a1, a2, a3, b0, b1);
            }
        }

        // ---- online softmax (base 2), convert P to tf32 in place ----
        float mloc0 = -1e30f, mloc1 = -1e30f;
        #pragma unroll
        for (int nt = 0; nt < 8; nt++) {
            mloc0 = fmaxf(mloc0, fmaxf(s[nt][0], s[nt][1]));
            mloc1 = fmaxf(mloc1, fmaxf(s[nt][2], s[nt][3]));
        }
        #pragma unroll
        for (int off = 1; off <= 2; off <<= 1) {
            mloc0 = fmaxf(mloc0, __shfl_xor_sync(0xffffffffu, mloc0, off));
            mloc1 = fmaxf(mloc1, __shfl_xor_sync(0xffffffffu, mloc1, off));
        }
        float mnew0 = fmaxf(m0, mloc0);
        float mnew1 = fmaxf(m1, mloc1);
        float alpha0 = exp2f(m0 - mnew0);
        float alpha1 = exp2f(m1 - mnew1);

        float rs0 = 0.0f, rs1 = 0.0f;
        #pragma unroll
        for (int nt = 0; nt < 8; nt++) {
            float p0 = exp2f(s[nt][0] - mnew0);
            float p1 = exp2f(s[nt][1] - mnew0);
            float p2 = exp2f(s[nt][2] - mnew1);
            float p3 = exp2f(s[nt][3] - mnew1);
            rs0 += p0 + p1;
            rs1 += p2 + p3;
            s[nt][0] = __uint_as_float(f2tf32(p0));
            s[nt][1] = __uint_as_float(f2tf32(p1));
            s[nt][2] = __uint_as_float(f2tf32(p2));
            s[nt][3] = __uint_as_float(f2tf32(p3));
        }
        #pragma unroll
        for (int off = 1; off <= 2; off <<= 1) {
            rs0 += __shfl_xor_sync(0xffffffffu, rs0, off);
            rs1 += __shfl_xor_sync(0xffffffffu, rs1, off);
        }
        l0 = l0 * alpha0 + rs0;
        l1 = l1 * alpha1 + rs1;
        m0 = mnew0;
        m1 = mnew1;
        #pragma unroll
        for (int nt = 0; nt < 8; nt++) {
            o[nt][0] *= alpha0; o[nt][1] *= alpha0;
            o[nt][2] *= alpha1; o[nt][3] *= alpha1;
        }

        // ---- O += P*V : A-fragment of P obtained via shuffles ----
        #pragma unroll
        for (int ks = 0; ks < 8; ks++) {
            unsigned p0 = __float_as_uint(s[ks][0]);
            unsigned p1 = __float_as_uint(s[ks][1]);
            unsigned p2 = __float_as_uint(s[ks][2]);
            unsigned p3 = __float_as_uint(s[ks][3]);
            unsigned t00 = __shfl_sync(0xffffffffu, p0, L0);
            unsigned t01 = __shfl_sync(0xffffffffu, p1, L0);
            unsigned t02 = __shfl_sync(0xffffffffu, p2, L0);
            unsigned t03 = __shfl_sync(0xffffffffu, p3, L0);
            unsigned t10 = __shfl_sync(0xffffffffu, p0, L1);
            unsigned t11 = __shfl_sync(0xffffffffu, p1, L1);
            unsigned t12 = __shfl_sync(0xffffffffu, p2, L1);
            unsigned t13 = __shfl_sync(0xffffffffu, p3, L1);
            unsigned a0 = sel ? t01 : t00;
            unsigned a1 = sel ? t03 : t02;
            unsigned a2 = sel ? t11 : t10;
            unsigned a3 = sel ? t13 : t12;
            int k0 = ks * 8;
            #pragma unroll
            for (int nt = 0; nt < 8; nt++) {
                unsigned b0 = V_[(k0 + lq) * AQ_STR + nt * 8 + lg];
                unsigned b1 = V_[(k0 + 4 + lq) * AQ_STR + nt * 8 + lg];
                mma_tf32(o[nt][0], o[nt][1], o[nt][2], o[nt][3], a0, a1, a2, a3, b0, b1);
            }
        }
        __syncthreads();
    }

    // epilogue
    float inv0 = 1.0f / l0;
    float inv1 = 1.0f / l1;
    int row = s0 + rbase + lg;
    #pragma unroll
    for (int nt = 0; nt < 8; nt++) {
        int col = h * DKK + nt * 8 + 2 * lq;
        float2 v0 = make_float2(__uint_as_float(f2tf32(o[nt][0] * inv0)),
                                __uint_as_float(f2tf32(o[nt][1] * inv0)));
        float2 v1 = make_float2(__uint_as_float(f2tf32(o[nt][2] * inv1)),
                                __uint_as_float(f2tf32(o[nt][3] * inv1)));
        *(float2*)(cat + (size_t)(b * SS + row) * DOUTT + col) = v0;
        *(float2*)(cat + (size_t)(b * SS + row + 8) * DOUTT + col) = v1;
    }
}

// ============================================================
// launch
// ============================================================
extern "C" void kernel_launch(void* const* d_in, const int* in_sizes, int n_in,
                              void* d_out, int out_size) {
    const float* x  = (const float*)d_in[0];
    const float* Wq = (const float*)d_in[1];
    const float* bq = (const float*)d_in[2];
    const float* Wk = (const float*)d_in[3];
    const float* bk = (const float*)d_in[4];
    const float* Wv = (const float*)d_in[5];
    const float* bv = (const float*)d_in[6];
    const float* Wo = (const float*)d_in[7];
    const float* bo = (const float*)d_in[8];
    float* out = (float*)d_out;

    float *pWqkv, *pbqkv, *pWo, *pxr, *pQKV, *pcat;
    cudaGetSymbolAddress((void**)&pWqkv, g_Wqkv);
    cudaGetSymbolAddress((void**)&pbqkv, g_bqkv);
    cudaGetSymbolAddress((void**)&pWo,   g_Wo);
    cudaGetSymbolAddress((void**)&pxr,   g_xr);
    cudaGetSymbolAddress((void**)&pQKV,  g_QKV);
    cudaGetSymbolAddress((void**)&pcat,  g_cat);

    {
        int n4 = MM * DD / 4;
        round_x_kernel<<<(n4 + 255) / 256, 256>>>(x);
    }
    {
        int total = 3 * DD * HH * DKK;
        pack_weights_kernel<<<(total + 255) / 256, 256>>>(Wq, bq, Wk, bk, Wv, bv, Wo);
    }
    {
        cudaFuncSetAttribute(gemm_tf32_p4, cudaFuncAttributeMaxDynamicSharedMemorySize,
                             GEMM_SMEM_WORDS * (int)sizeof(unsigned));
        dim3 grid(N3 / 128, MM / 128);
        gemm_tf32_p4<<<grid, 256, GEMM_SMEM_WORDS * sizeof(unsigned)>>>(
            pxr, pWqkv, pbqkv, pQKV, MM, N3, DD, 1);
    }
    {
        cudaFuncSetAttribute(attn_tc3, cudaFuncAttributeMaxDynamicSharedMemorySize,
                             ATT_SMEM_WORDS * (int)sizeof(unsigned));
        dim3 grid(SS / 128, BB * HH);
        attn_tc3<<<grid, 256, ATT_SMEM_WORDS * sizeof(unsigned)>>>(pQKV, pcat);
    }
    {
        dim3 grid(DOUTT / 128, MM / 128);
        gemm_tf32_p4<<<grid, 256, GEMM_SMEM_WORDS * sizeof(unsigned)>>>(
            pcat, pWo, bo, out, MM, DOUTT, DD, 0);
    }
}

// round 5
// speedup vs baseline: 3.8101x; 1.1132x over previous
#include <cuda_runtime.h>
#include <math.h>
#include <stdint.h>

#define BB   4
#define SS   2048
#define DD   1024
#define HH   16
#define DKK  64
#define DOUTT 1024
#define MM   (BB*SS)
#define N3   (3*HH*DKK)

// -------- scratch --------
__device__ float g_Wqkv[DD * N3];
__device__ float g_bqkv[N3];
__device__ float g_Wo[DD * DOUTT];
__device__ float g_xr[(size_t)MM * DD];
__device__ float g_QKV[(size_t)MM * N3];
__device__ float g_cat[(size_t)MM * DOUTT];

__device__ __forceinline__ unsigned f2tf32(float x) {
    unsigned r;
    asm("cvt.rna.tf32.f32 %0, %1;" : "=r"(r) : "f"(x));
    return r;
}

__device__ __forceinline__ void mma_tf32(float& c0, float& c1, float& c2, float& c3,
                                         unsigned a0, unsigned a1, unsigned a2, unsigned a3,
                                         unsigned b0, unsigned b1) {
    asm volatile(
        "mma.sync.aligned.m16n8k8.row.col.f32.tf32.tf32.f32 "
        "{%0,%1,%2,%3}, {%4,%5,%6,%7}, {%8,%9}, {%0,%1,%2,%3};\n"
        : "+f"(c0), "+f"(c1), "+f"(c2), "+f"(c3)
        : "r"(a0), "r"(a1), "r"(a2), "r"(a3), "r"(b0), "r"(b1));
}

__device__ __forceinline__ void cp16(unsigned* smem_ptr, const float* gmem_ptr) {
    unsigned dst = (unsigned)__cvta_generic_to_shared(smem_ptr);
    asm volatile("cp.async.cg.shared.global [%0], [%1], 16;\n" :: "r"(dst), "l"(gmem_ptr));
}
#define CP_COMMIT() asm volatile("cp.async.commit_group;\n" ::: "memory")
#define CP_WAIT(n)  asm volatile("cp.async.wait_group %0;\n" :: "n"(n) : "memory")

// ============================================================
// Kernel 0: round x to tf32 grid
// ============================================================
__global__ void round_x_kernel(const float* __restrict__ x) {
    size_t i = (size_t)(blockIdx.x * blockDim.x + threadIdx.x) * 4;
    if (i < (size_t)MM * DD) {
        float4 v = *(const float4*)(x + i);
        float4 o;
        o.x = __uint_as_float(f2tf32(v.x));
        o.y = __uint_as_float(f2tf32(v.y));
        o.z = __uint_as_float(f2tf32(v.z));
        o.w = __uint_as_float(f2tf32(v.w));
        *(float4*)(g_xr + i) = o;
    }
}

// ============================================================
// Kernel 1: pack+round weights
// ============================================================
__global__ void pack_weights_kernel(const float* __restrict__ Wq,
                                    const float* __restrict__ bq,
                                    const float* __restrict__ Wk,
                                    const float* __restrict__ bk,
                                    const float* __restrict__ Wv,
                                    const float* __restrict__ bv,
                                    const float* __restrict__ Wo) {
    int idx = blockIdx.x * blockDim.x + threadIdx.x;
    const int per = DD * HH * DKK;
    if (idx < 3 * per) {
        int which = idx / per;
        int rem   = idx % per;
        int d = rem >> 10;
        int c = rem & 1023;
        int h = c >> 6;
        int k = c & 63;
        const float* W = (which == 0) ? Wq : (which == 1) ? Wk : Wv;
        g_Wqkv[(size_t)d * N3 + which * 1024 + c] =
            __uint_as_float(f2tf32(W[h * (DD * DKK) + d * DKK + k]));
    }
    if (idx < N3) {
        int which = idx >> 10;
        int c = idx & 1023;
        const float* bsrc = (which == 0) ? bq : (which == 1) ? bk : bv;
        g_bqkv[idx] = bsrc[c];
    }
    if (idx < DD * DOUTT) {
        g_Wo[idx] = __uint_as_float(f2tf32(Wo[idx]));
    }
}

// ============================================================
// Kernel 2: TF32 GEMM, 4-stage cp.async pipeline (unchanged).
// ============================================================
#define GA_STR 20
#define GB_STR 136
#define G_STAGE_A (128 * GA_STR)
#define G_STAGE_B (16 * GB_STR)
#define GEMM_SMEM_WORDS (4 * (G_STAGE_A + G_STAGE_B))

__global__ __launch_bounds__(256, 2) void gemm_tf32_p4(
    const float* __restrict__ A, const float* __restrict__ Bw,
    const float* __restrict__ bias, float* __restrict__ C,
    int M, int N, int K, int round_out)
{
    extern __shared__ unsigned gsm[];
    unsigned* As = gsm;
    unsigned* Bs = gsm + 4 * G_STAGE_A;

    int tid  = threadIdx.x;
    int lane = tid & 31;
    int w    = tid >> 5;
    int warp_m = w >> 1;
    int warp_n = w & 1;
    int lg = lane >> 2;
    int lq = lane & 3;

    const float* Aptr = A + (size_t)(blockIdx.y * 128) * K;
    const float* Bptr = Bw + blockIdx.x * 128;

    int ar  = tid >> 2;
    int akk = (tid & 3) << 2;
    int bkk = tid >> 5;
    int bn4 = (tid & 31) << 2;

    int ntk = K >> 4;

    #pragma unroll
    for (int ps = 0; ps < 3; ps++) {
        int kt = ps << 4;
        unsigned* Asp = As + ps * G_STAGE_A;
        unsigned* Bsp = Bs + ps * G_STAGE_B;
        cp16(&Asp[ar * GA_STR + akk],        Aptr + (size_t)ar * K + kt + akk);
        cp16(&Asp[(ar + 64) * GA_STR + akk], Aptr + (size_t)(ar + 64) * K + kt + akk);
        cp16(&Bsp[bkk * GB_STR + bn4],       Bptr + (size_t)(kt + bkk) * N + bn4);
        cp16(&Bsp[(bkk + 8) * GB_STR + bn4], Bptr + (size_t)(kt + bkk + 8) * N + bn4);
        CP_COMMIT();
    }

    float acc[2][8][4];
    #pragma unroll
    for (int mt = 0; mt < 2; mt++)
        #pragma unroll
        for (int nt = 0; nt < 8; nt++)
            #pragma unroll
            for (int r = 0; r < 4; r++) acc[mt][nt][r] = 0.0f;

    for (int t = 0; t < ntk; t++) {
        if (t + 3 < ntk) {
            int kt = (t + 3) << 4;
            int ns = (t + 3) & 3;
            unsigned* Asp = As + ns * G_STAGE_A;
            unsigned* Bsp = Bs + ns * G_STAGE_B;
            cp16(&Asp[ar * GA_STR + akk],        Aptr + (size_t)ar * K + kt + akk);
            cp16(&Asp[(ar + 64) * GA_STR + akk], Aptr + (size_t)(ar + 64) * K + kt + akk);
            cp16(&Bsp[bkk * GB_STR + bn4],       Bptr + (size_t)(kt + bkk) * N + bn4);
            cp16(&Bsp[(bkk + 8) * GB_STR + bn4], Bptr + (size_t)(kt + bkk + 8) * N + bn4);
            CP_COMMIT();
        }
        CP_WAIT(2);
        __syncthreads();

        const unsigned* Asl = As + (t & 3) * G_STAGE_A;
        const unsigned* Bsl = Bs + (t & 3) * G_STAGE_B;
        #pragma unroll
        for (int ks = 0; ks < 2; ks++) {
            int k0 = ks * 8;
            unsigned af[2][4];
            #pragma unroll
            for (int mt = 0; mt < 2; mt++) {
                int mb = warp_m * 32 + mt * 16;
                af[mt][0] = Asl[(mb + lg) * GA_STR + k0 + lq];
                af[mt][1] = Asl[(mb + 8 + lg) * GA_STR + k0 + lq];
                af[mt][2] = Asl[(mb + lg) * GA_STR + k0 + 4 + lq];
                af[mt][3] = Asl[(mb + 8 + lg) * GA_STR + k0 + 4 + lq];
            }
            #pragma unroll
            for (int nt = 0; nt < 8; nt++) {
                int nb = warp_n * 64 + nt * 8;
                unsigned b0 = Bsl[(k0 + lq) * GB_STR + nb + lg];
                unsigned b1 = Bsl[(k0 + 4 + lq) * GB_STR + nb + lg];
                #pragma unroll
                for (int mt = 0; mt < 2; mt++)
                    mma_tf32(acc[mt][nt][0], acc[mt][nt][1], acc[mt][nt][2], acc[mt][nt][3],
                             af[mt][0], af[mt][1], af[mt][2], af[mt][3], b0, b1);
            }
        }
        __syncthreads();
    }

    #pragma unroll
    for (int mt = 0; mt < 2; mt++) {
        int row0 = blockIdx.y * 128 + warp_m * 32 + mt * 16 + lg;
        #pragma unroll
        for (int nt = 0; nt < 8; nt++) {
            int col = blockIdx.x * 128 + warp_n * 64 + nt * 8 + 2 * lq;
            float b0 = bias[col], b1 = bias[col + 1];
            float r00 = acc[mt][nt][0] + b0, r01 = acc[mt][nt][1] + b1;
            float r10 = acc[mt][nt][2] + b0, r11 = acc[mt][nt][3] + b1;
            if (round_out) {
                r00 = __uint_as_float(f2tf32(r00));
                r01 = __uint_as_float(f2tf32(r01));
                r10 = __uint_as_float(f2tf32(r10));
                r11 = __uint_as_float(f2tf32(r11));
            }
            *(float2*)(C + (size_t)row0 * N + col) = make_float2(r00, r01);
            *(float2*)(C + (size_t)(row0 + 8) * N + col) = make_float2(r10, r11);
        }
    }
}

// ============================================================
// Kernel 3: flash attention v4.
// block 128 (4 warps), Q tile 128 rows, warp tile 32x64 (2 m-tiles),
// KV 64-key tiles double-buffered, P via register shuffles.
// ============================================================
#define AQ_STR 68
#define ATT_SMEM_WORDS (128*AQ_STR + 2*64*AQ_STR + 2*64*AQ_STR)

__global__ __launch_bounds__(128, 2) void attn_tc4(const float* __restrict__ QKV,
                                                   float* __restrict__ cat)
{
    extern __shared__ unsigned sm[];
    unsigned* Qs = sm;                    // [128][68]
    unsigned* Ks = sm + 128 * AQ_STR;     // [2][64][68]
    unsigned* Vs = Ks + 2 * 64 * AQ_STR;  // [2][64][68]

    int tid  = threadIdx.x;
    int lane = tid & 31;
    int w    = tid >> 5;          // 0..3
    int lg = lane >> 2;
    int lq = lane & 3;
    int rbase = w * 32;           // warp owns q-rows rbase..rbase+31

    int bh = blockIdx.y;
    int b = bh >> 4;
    int h = bh & 15;
    int s0 = blockIdx.x * 128;

    const float* Qbase = QKV + (size_t)(b * SS) * N3 + h * DKK;
    const float* Kbase = Qbase + 1024;
    const float* Vbase = Qbase + 2048;

    int kvr  = tid >> 4;                // 0..7
    int kvc4 = (tid & 15) << 2;

    // prefetch KV tile 0 (64 rows, 8 rows per pass)
    #pragma unroll
    for (int L = 0; L < 8; L++) {
        int r = kvr + L * 8;
        cp16(&Ks[r * AQ_STR + kvc4], Kbase + (size_t)r * N3 + kvc4);
        cp16(&Vs[r * AQ_STR + kvc4], Vbase + (size_t)r * N3 + kvc4);
    }
    CP_COMMIT();

    // load Q tile (128x64), scale by (1/8)*log2(e), round to tf32
    const float QSC = 0.18033688011112042f;
    #pragma unroll
    for (int L = 0; L < 16; L++) {
        int idx = tid + L * 128;
        int r  = idx >> 4;
        int c4 = (idx & 15) << 2;
        float4 v = *(const float4*)(Qbase + (size_t)(s0 + r) * N3 + c4);
        Qs[r * AQ_STR + c4 + 0] = f2tf32(v.x * QSC);
        Qs[r * AQ_STR + c4 + 1] = f2tf32(v.y * QSC);
        Qs[r * AQ_STR + c4 + 2] = f2tf32(v.z * QSC);
        Qs[r * AQ_STR + c4 + 3] = f2tf32(v.w * QSC);
    }

    float o[2][8][4];
    #pragma unroll
    for (int mt = 0; mt < 2; mt++)
        #pragma unroll
        for (int nt = 0; nt < 8; nt++)
            #pragma unroll
            for (int r = 0; r < 4; r++) o[mt][nt][r] = 0.0f;
    float mrun[2][2] = {{-1e30f, -1e30f}, {-1e30f, -1e30f}};
    float lrun[2][2] = {{0.0f, 0.0f}, {0.0f, 0.0f}};

    // shuffle source lanes for S->A fragment conversion
    int L0 = (lane & ~3) | (lq >> 1);
    int L1 = L0 + 2;
    bool sel = (lq & 1);

    const int NT = SS / 64;
    for (int t = 0; t < NT; t++) {
        int st = t & 1;
        if (t + 1 < NT) {
            int kt = (t + 1) * 64;
            unsigned* Kn = Ks + (st ^ 1) * 64 * AQ_STR;
            unsigned* Vn = Vs + (st ^ 1) * 64 * AQ_STR;
            #pragma unroll
            for (int L = 0; L < 8; L++) {
                int r = kvr + L * 8;
                cp16(&Kn[r * AQ_STR + kvc4], Kbase + (size_t)(kt + r) * N3 + kvc4);
                cp16(&Vn[r * AQ_STR + kvc4], Vbase + (size_t)(kt + r) * N3 + kvc4);
            }
            CP_COMMIT();
            CP_WAIT(1);
        } else {
            CP_WAIT(0);
        }
        __syncthreads();

        const unsigned* K_ = Ks + st * 64 * AQ_STR;
        const unsigned* V_ = Vs + st * 64 * AQ_STR;

        // ---- S = Q*K^T (warp: 32 q-rows x 64 keys), base-2 scaled ----
        float s[2][8][4];
        #pragma unroll
        for (int mt = 0; mt < 2; mt++)
            #pragma unroll
            for (int nt = 0; nt < 8; nt++)
                #pragma unroll
                for (int r = 0; r < 4; r++) s[mt][nt][r] = 0.0f;

        #pragma unroll
        for (int ks = 0; ks < 8; ks++) {
            int k0 = ks * 8;
            unsigned af[2][4];
            #pragma unroll
            for (int mt = 0; mt < 2; mt++) {
                int mb = rbase + mt * 16;
                af[mt][0] = Qs[(mb + lg) * AQ_STR + k0 + lq];
                af[mt][1] = Qs[(mb + 8 + lg) * AQ_STR + k0 + lq];
                af[mt][2] = Qs[(mb + lg) * AQ_STR + k0 + 4 + lq];
                af[mt][3] = Qs[(mb + 8 + lg) * AQ_STR + k0 + 4 + lq];
            }
            #pragma unroll
            for (int nt = 0; nt < 8; nt++) {
                unsigned b0 = K_[(nt * 8 + lg) * AQ_STR + k0 + lq];
                unsigned b1 = K_[(nt * 8 + lg) * AQ_STR + k0 + 4 + lq];
                #pragma unroll
                for (int mt = 0; mt < 2; mt++)
                    mma_tf32(s[mt][nt][0], s[mt][nt][1], s[mt][nt][2], s[mt][nt][3],
                             af[mt][0], af[mt][1], af[mt][2], af[mt][3], b0, b1);
            }
        }

        // ---- online softmax (base 2), per m-tile; convert P to tf32 ----
        #pragma unroll
        for (int mt = 0; mt < 2; mt++) {
            float mloc0 = -1e30f, mloc1 = -1e30f;
            #pragma unroll
            for (int nt = 0; nt < 8; nt++) {
                mloc0 = fmaxf(mloc0, fmaxf(s[mt][nt][0], s[mt][nt][1]));
                mloc1 = fmaxf(mloc1, fmaxf(s[mt][nt][2], s[mt][nt][3]));
            }
            #pragma unroll
            for (int off = 1; off <= 2; off <<= 1) {
                mloc0 = fmaxf(mloc0, __shfl_xor_sync(0xffffffffu, mloc0, off));
                mloc1 = fmaxf(mloc1, __shfl_xor_sync(0xffffffffu, mloc1, off));
            }
            float mnew0 = fmaxf(mrun[mt][0], mloc0);
            float mnew1 = fmaxf(mrun[mt][1], mloc1);
            float alpha0 = exp2f(mrun[mt][0] - mnew0);
            float alpha1 = exp2f(mrun[mt][1] - mnew1);

            float rs0 = 0.0f, rs1 = 0.0f;
            #pragma unroll
            for (int nt = 0; nt < 8; nt++) {
                float p0 = exp2f(s[mt][nt][0] - mnew0);
                float p1 = exp2f(s[mt][nt][1] - mnew0);
                float p2 = exp2f(s[mt][nt][2] - mnew1);
                float p3 = exp2f(s[mt][nt][3] - mnew1);
                rs0 += p0 + p1;
                rs1 += p2 + p3;
                s[mt][nt][0] = __uint_as_float(f2tf32(p0));
                s[mt][nt][1] = __uint_as_float(f2tf32(p1));
                s[mt][nt][2] = __uint_as_float(f2tf32(p2));
                s[mt][nt][3] = __uint_as_float(f2tf32(p3));
            }
            #pragma unroll
            for (int off = 1; off <= 2; off <<= 1) {
                rs0 += __shfl_xor_sync(0xffffffffu, rs0, off);
                rs1 += __shfl_xor_sync(0xffffffffu, rs1, off);
            }
            lrun[mt][0] = lrun[mt][0] * alpha0 + rs0;
            lrun[mt][1] = lrun[mt][1] * alpha1 + rs1;
            mrun[mt][0] = mnew0;
            mrun[mt][1] = mnew1;
            #pragma unroll
            for (int nt = 0; nt < 8; nt++) {
                o[mt][nt][0] *= alpha0; o[mt][nt][1] *= alpha0;
                o[mt][nt][2] *= alpha1; o[mt][nt][3] *= alpha1;
            }
        }

        // ---- O += P*V : P A-fragments via shuffles; V frags shared over mt ----
        #pragma unroll
        for (int ks = 0; ks < 8; ks++) {
            unsigned af[2][4];
            #pragma unroll
            for (int mt = 0; mt < 2; mt++) {
                unsigned p0 = __float_as_uint(s[mt][ks][0]);
                unsigned p1 = __float_as_uint(s[mt][ks][1]);
                unsigned p2 = __float_as_uint(s[mt][ks][2]);
                unsigned p3 = __float_as_uint(s[mt][ks][3]);
                unsigned t00 = __shfl_sync(0xffffffffu, p0, L0);
                unsigned t01 = __shfl_sync(0xffffffffu, p1, L0);
                unsigned t02 = __shfl_sync(0xffffffffu, p2, L0);
                unsigned t03 = __shfl_sync(0xffffffffu, p3, L0);
                unsigned t10 = __shfl_sync(0xffffffffu, p0, L1);
                unsigned t11 = __shfl_sync(0xffffffffu, p1, L1);
                unsigned t12 = __shfl_sync(0xffffffffu, p2, L1);
                unsigned t13 = __shfl_sync(0xffffffffu, p3, L1);
                af[mt][0] = sel ? t01 : t00;
                af[mt][1] = sel ? t03 : t02;
                af[mt][2] = sel ? t11 : t10;
                af[mt][3] = sel ? t13 : t12;
            }
            int k0 = ks * 8;
            #pragma unroll
            for (int nt = 0; nt < 8; nt++) {
                unsigned b0 = V_[(k0 + lq) * AQ_STR + nt * 8 + lg];
                unsigned b1 = V_[(k0 + 4 + lq) * AQ_STR + nt * 8 + lg];
                #pragma unroll
                for (int mt = 0; mt < 2; mt++)
                    mma_tf32(o[mt][nt][0], o[mt][nt][1], o[mt][nt][2], o[mt][nt][3],
                             af[mt][0], af[mt][1], af[mt][2], af[mt][3], b0, b1);
            }
        }
        __syncthreads();
    }

    // epilogue
    #pragma unroll
    for (int mt = 0; mt < 2; mt++) {
        float inv0 = 1.0f / lrun[mt][0];
        float inv1 = 1.0f / lrun[mt][1];
        int row = s0 + rbase + mt * 16 + lg;
        #pragma unroll
        for (int nt = 0; nt < 8; nt++) {
            int col = h * DKK + nt * 8 + 2 * lq;
            float2 v0 = make_float2(__uint_as_float(f2tf32(o[mt][nt][0] * inv0)),
                                    __uint_as_float(f2tf32(o[mt][nt][1] * inv0)));
            float2 v1 = make_float2(__uint_as_float(f2tf32(o[mt][nt][2] * inv1)),
                                    __uint_as_float(f2tf32(o[mt][nt][3] * inv1)));
            *(float2*)(cat + (size_t)(b * SS + row) * DOUTT + col) = v0;
            *(float2*)(cat + (size_t)(b * SS + row + 8) * DOUTT + col) = v1;
        }
    }
}

// ============================================================
// launch
// ============================================================
extern "C" void kernel_launch(void* const* d_in, const int* in_sizes, int n_in,
                              void* d_out, int out_size) {
    const float* x  = (const float*)d_in[0];
    const float* Wq = (const float*)d_in[1];
    const float* bq = (const float*)d_in[2];
    const float* Wk = (const float*)d_in[3];
    const float* bk = (const float*)d_in[4];
    const float* Wv = (const float*)d_in[5];
    const float* bv = (const float*)d_in[6];
    const float* Wo = (const float*)d_in[7];
    const float* bo = (const float*)d_in[8];
    float* out = (float*)d_out;

    float *pWqkv, *pbqkv, *pWo, *pxr, *pQKV, *pcat;
    cudaGetSymbolAddress((void**)&pWqkv, g_Wqkv);
    cudaGetSymbolAddress((void**)&pbqkv, g_bqkv);
    cudaGetSymbolAddress((void**)&pWo,   g_Wo);
    cudaGetSymbolAddress((void**)&pxr,   g_xr);
    cudaGetSymbolAddress((void**)&pQKV,  g_QKV);
    cudaGetSymbolAddress((void**)&pcat,  g_cat);

    {
        int n4 = MM * DD / 4;
        round_x_kernel<<<(n4 + 255) / 256, 256>>>(x);
    }
    {
        int total = 3 * DD * HH * DKK;
        pack_weights_kernel<<<(total + 255) / 256, 256>>>(Wq, bq, Wk, bk, Wv, bv, Wo);
    }
    {
        cudaFuncSetAttribute(gemm_tf32_p4, cudaFuncAttributeMaxDynamicSharedMemorySize,
                             GEMM_SMEM_WORDS * (int)sizeof(unsigned));
        dim3 grid(N3 / 128, MM / 128);
        gemm_tf32_p4<<<grid, 256, GEMM_SMEM_WORDS * sizeof(unsigned)>>>(
            pxr, pWqkv, pbqkv, pQKV, MM, N3, DD, 1);
    }
    {
        cudaFuncSetAttribute(attn_tc4, cudaFuncAttributeMaxDynamicSharedMemorySize,
                             ATT_SMEM_WORDS * (int)sizeof(unsigned));
        dim3 grid(SS / 128, BB * HH);
        attn_tc4<<<grid, 128, ATT_SMEM_WORDS * sizeof(unsigned)>>>(pQKV, pcat);
    }
    {
        dim3 grid(DOUTT / 128, MM / 128);
        gemm_tf32_p4<<<grid, 256, GEMM_SMEM_WORDS * sizeof(unsigned)>>>(
            pcat, pWo, bo, out, MM, DOUTT, DD, 0);
    }
}